// round 12
// baseline (speedup 1.0000x reference)
#include <cuda_runtime.h>
#include <math.h>

// Problem constants
#define BSX   2
#define QL    64
#define KLN   64
#define NH    8
#define DKV   64
#define INNER 512
#define VOC   4096
#define NBH   16          // BSX * NH
#define VSPL  64          // v-range splits (64 v each)

// Masks (all scratch arrays are power-of-2 element counts)
#define M_PROJ 0xFFFFu     // 65536
#define M_DICT 0x3FFFFu    // 262144
#define M_AB   0x3FFFFFu   // 4194304
#define M_NRM  0x3FFu      // 1024
#define M_G    0xFFFFu     // 65536
#define M_P    0x3FFFFFu   // 4194304
#define M_W    0xFFFFu     // 65536

typedef unsigned long long u64;
#define ADD_F32X2(out, a, b) \
    asm("add.rn.f32x2 %0, %1, %2;" : "=l"(out) : "l"(a), "l"(b))
#define FMA_F32X2(out, a, b, c) \
    asm("fma.rn.f32x2 %0, %1, %2, %3;" : "=l"(out) : "l"(a), "l"(b), "l"(c))
#define PACK_DUP(out, x) \
    asm("mov.b64 %0, {%1, %1};" : "=l"(out) : "f"(x))

// ---------------- scratch (device globals; no allocation allowed) -------------
__device__ float g_qproj[BSX * QL * INNER];        // 65536
__device__ float g_kproj[BSX * KLN * INNER];       // 65536
__device__ float g_dnT[DKV * VOC];                 // l2 dict [d][v]  262144
__device__ float g_dp[VOC * DKV];                  // LN(dict)@O      262144
__device__ float g_A[NBH * QL * VOC];              // 4194304
__device__ float g_Bm[NBH * KLN * VOC];            // 4194304
__device__ float g_nq[NBH * QL];                   // 1024
__device__ float g_nk[NBH * KLN];                  // 1024
__device__ float g_G[NBH * QL * KLN];              // 65536
__device__ float g_pv[NBH * QL * KLN * VSPL];      // 4194304
__device__ float g_ws[NBH * QL * KLN];             // 65536
__device__ int   g_id[NBH * QL * KLN];             // 65536

// ---------------- K0: dict preprocessing (l2norm(T) + LN@O) -------------------
__global__ void k0_dict(const float* __restrict__ dict,
                        const float* __restrict__ vg,
                        const float* __restrict__ vb,
                        const float* __restrict__ O) {
    __shared__ float sn[64][65];                       // [d][vlocal]
    int l = threadIdx.x & 31, warp = threadIdx.x >> 5;
    int v0 = blockIdx.x * 64;
    #pragma unroll
    for (int i = 0; i < 8; i++) {
        int vl = warp * 8 + i;
        int r = v0 + vl;
        float x0 = dict[(r * DKV + l) & M_DICT];
        float x1 = dict[(r * DKV + 32 + l) & M_DICT];

        float s = x0 * x0 + x1 * x1;
        #pragma unroll
        for (int o = 16; o > 0; o >>= 1) s += __shfl_xor_sync(0xffffffffu, s, o);
        float inv = rsqrtf(fmaxf(s, 1e-12f));
        sn[l][vl]      = x0 * inv;
        sn[l + 32][vl] = x1 * inv;

        float m = x0 + x1;
        #pragma unroll
        for (int o = 16; o > 0; o >>= 1) m += __shfl_xor_sync(0xffffffffu, m, o);
        m *= (1.0f / 64.0f);
        float d0 = x0 - m, d1 = x1 - m;
        float v = d0 * d0 + d1 * d1;
        #pragma unroll
        for (int o = 16; o > 0; o >>= 1) v += __shfl_xor_sync(0xffffffffu, v, o);
        v *= (1.0f / 64.0f);
        float rs = rsqrtf(v + 1e-6f);
        float ln0 = d0 * rs * vg[l & 63]        + vb[l & 63];
        float ln1 = d1 * rs * vg[(l + 32) & 63] + vb[(l + 32) & 63];

        float a0 = 0.f, a1 = 0.f;
        #pragma unroll
        for (int d2 = 0; d2 < 32; d2++) {
            float t = __shfl_sync(0xffffffffu, ln0, d2);
            a0 += t * O[(d2 * 64 + l) & 4095];
            a1 += t * O[(d2 * 64 + 32 + l) & 4095];
        }
        #pragma unroll
        for (int d2 = 0; d2 < 32; d2++) {
            float t = __shfl_sync(0xffffffffu, ln1, d2);
            a0 += t * O[((32 + d2) * 64 + l) & 4095];
            a1 += t * O[((32 + d2) * 64 + 32 + l) & 4095];
        }
        g_dp[(r * DKV + l) & M_DICT]      = a0;
        g_dp[(r * DKV + 32 + l) & M_DICT] = a1;
    }
    __syncthreads();
    for (int i = threadIdx.x; i < 64 * 64; i += 256) {
        int d = i >> 6, vl = i & 63;
        g_dnT[(d * VOC + v0 + vl) & M_DICT] = sn[d][vl];
    }
}

// ---------------- K1: q_proj / k_proj GEMM ------------------------------------
__global__ void k1_proj(const float* __restrict__ q, const float* __restrict__ k,
                        const float* __restrict__ qpe, const float* __restrict__ kpe,
                        const float* __restrict__ wi) {
    __shared__ __align__(16) float xs[8][INNER];
    int side = blockIdx.z;
    const float* xin = side ? k   : q;
    const float* pin = side ? kpe : qpe;
    const float* W   = wi + side * (INNER * INNER);
    float* out = side ? g_kproj : g_qproj;
    int m0 = blockIdx.y * 8;
    int tid = threadIdx.x;                             // 128 threads
    for (int i = tid; i < 8 * INNER; i += 128) {
        int r = i >> 9, d = i & 511;
        int gidx = ((m0 + r) * INNER + d) & M_PROJ;
        xs[r][d] = xin[gidx] + pin[gidx];
    }
    __syncthreads();
    int e  = blockIdx.x * 64 + (tid & 63);             // 0..511
    int r0 = (tid >> 6) * 4;                           // 0 or 4
    float acc[4] = {};
    for (int d = 0; d < INNER; d += 4) {
        float w0 = W[((d + 0) * INNER + e) & 0x3FFFF];
        float w1 = W[((d + 1) * INNER + e) & 0x3FFFF];
        float w2 = W[((d + 2) * INNER + e) & 0x3FFFF];
        float w3 = W[((d + 3) * INNER + e) & 0x3FFFF];
        #pragma unroll
        for (int r = 0; r < 4; r++) {
            float4 xv = *(const float4*)&xs[r0 + r][d];
            acc[r] += xv.x * w0 + xv.y * w1 + xv.z * w2 + xv.w * w3;
        }
    }
    #pragma unroll
    for (int r = 0; r < 4; r++)
        out[((m0 + r0 + r) * INNER + e) & M_PROJ] = acc[r];
}

// ---------------- K1c: per-head Gram + norms; grid (4 qt, 16 bh) --------------
__global__ void k1c_gram() {
    __shared__ float qs[16][65];
    __shared__ float ks[64][65];
    int qt = blockIdx.x;                               // 0..3
    int bh = blockIdx.y;                               // 0..15
    int b = bh >> 3, h = bh & 7;
    int tid = threadIdx.x;                             // 256
    for (int i = tid; i < 16 * 64; i += 256) {
        int r = i >> 6, d = i & 63;
        qs[r][d] = g_qproj[((b * 64 + qt * 16 + r) * INNER + h * 64 + d) & M_PROJ];
    }
    for (int i = tid; i < 64 * 64; i += 256) {
        int r = i >> 6, d = i & 63;
        ks[r][d] = g_kproj[((b * 64 + r) * INNER + h * 64 + d) & M_PROJ];
    }
    __syncthreads();
    int qq = tid >> 4;                                 // 0..15
    int kb = (tid & 15) * 4;                           // 4 k each
    float acc[4] = {};
    for (int d = 0; d < 64; d++) {
        float a = qs[qq][d];
        #pragma unroll
        for (int j = 0; j < 4; j++) acc[j] += a * ks[kb + j][d];
    }
    #pragma unroll
    for (int j = 0; j < 4; j++)
        g_G[((bh * 64 + qt * 16 + qq) * 64 + kb + j) & M_G] = acc[j];
    if (tid < 16) {
        float s = 0.f;
        #pragma unroll 8
        for (int d = 0; d < 64; d++) { float x = qs[tid][d]; s += x * x; }
        g_nq[(bh * 64 + qt * 16 + tid) & M_NRM] = s;
    } else if (qt == 0 && tid >= 64 && tid < 128) {
        int r = tid - 64;
        float s = 0.f;
        #pragma unroll 8
        for (int d = 0; d < 64; d++) { float x = ks[r][d]; s += x * x; }
        g_nk[(bh * 64 + r) & M_NRM] = s;
    }
}

// ---------------- K23: fused GEMM (FFMA2) + conflict-free max -----------------
// block = (64-v chunk, bh); 256 threads; 4 blocks/SM.
__global__ void __launch_bounds__(256, 4) k23_ab_max() {
    __shared__ union SU {
        struct { float xsT[32][132]; float dst[32][68]; } p1;  // GEMM inputs
        float Ps[128][68];                                     // GEMM outputs (16B rows)
    } su;
    int vc = blockIdx.x;                               // 0..63
    int bh = blockIdx.y;                               // 0..15
    int b = bh >> 3, h = bh & 7;
    int v0 = vc * 64;
    int tid = threadIdx.x;                             // 256
    int tv = tid & 7, tr = tid >> 3;                   // 8 v-groups x 32 row-groups
    u64 acc2[4][4] = {};                               // 4 rows x 4 v-pairs (packed)

    #pragma unroll
    for (int c = 0; c < 2; c++) {
        __syncthreads();
        for (int i = tid; i < 128 * 8; i += 256) {
            int r = i >> 3, d4 = (i & 7) * 4;
            const float* src = (r < 64) ? g_qproj : g_kproj;
            int g = ((b * 64 + (r & 63)) * INNER + h * 64 + c * 32 + d4) & (M_PROJ & ~3u);
            float4 vv = *(const float4*)&src[g];
            su.p1.xsT[d4 + 0][r] = vv.x; su.p1.xsT[d4 + 1][r] = vv.y;
            su.p1.xsT[d4 + 2][r] = vv.z; su.p1.xsT[d4 + 3][r] = vv.w;
        }
        for (int i = tid; i < 32 * 16; i += 256) {
            int d = i >> 4, m4 = (i & 15) * 4;
            int g = ((c * 32 + d) * VOC + v0 + m4) & (M_DICT & ~3u);
            *(float4*)&su.p1.dst[d][m4] = *(const float4*)&g_dnT[g];
        }
        __syncthreads();
        #pragma unroll 4
        for (int d = 0; d < 32; d++) {
            float4 xv = *(const float4*)&su.p1.xsT[d][tr * 4];
            ulonglong2 d0 = *(const ulonglong2*)&su.p1.dst[d][tv * 8];
            ulonglong2 d1 = *(const ulonglong2*)&su.p1.dst[d][tv * 8 + 4];
            float xa[4] = {xv.x, xv.y, xv.z, xv.w};
            #pragma unroll
            for (int i = 0; i < 4; i++) {
                u64 ap; PACK_DUP(ap, xa[i]);
                FMA_F32X2(acc2[i][0], ap, d0.x, acc2[i][0]);
                FMA_F32X2(acc2[i][1], ap, d0.y, acc2[i][1]);
                FMA_F32X2(acc2[i][2], ap, d1.x, acc2[i][2]);
                FMA_F32X2(acc2[i][3], ap, d1.y, acc2[i][3]);
            }
        }
    }
    __syncthreads();                                   // done with p1; reuse as Ps
    #pragma unroll
    for (int i = 0; i < 4; i++) {
        int r = tr * 4 + i;                            // 0..127
        ulonglong2 s0; s0.x = acc2[i][0]; s0.y = acc2[i][1];
        ulonglong2 s1; s1.x = acc2[i][2]; s1.y = acc2[i][3];
        *(ulonglong2*)&su.Ps[r][tv * 8]     = s0;
        *(ulonglong2*)&su.Ps[r][tv * 8 + 4] = s1;
        float* out = (r < 64) ? g_A : g_Bm;
        int base = ((bh * 64 + (r & 63)) * VOC + v0 + tv * 8) & (M_AB & ~3u);
        *(ulonglong2*)&out[base]     = s0;
        *(ulonglong2*)&out[base + 4] = s1;
    }
    __syncthreads();

    // max phase: conflict-free mapping. thread = (tq8, tk32):
    //   q rows = tq8 + 8i (i<8)  [per-warp gather = 8 consecutive rows -> 1 wf]
    //   k rows = tk32 + 32j (j<2)[per-warp gather = 4 rows -> 1 wf]
    int tq8 = tid & 7, tk32 = tid >> 3;
    float best[8][2];
    #pragma unroll
    for (int i = 0; i < 8; i++) { best[i][0] = -3.402823466e38f; best[i][1] = -3.402823466e38f; }
    for (int v = 0; v < 64; v += 4) {
        ulonglong2 b0 = *(const ulonglong2*)&su.Ps[64 + tk32][v];
        ulonglong2 b1 = *(const ulonglong2*)&su.Ps[96 + tk32][v];
        #pragma unroll
        for (int i = 0; i < 8; i++) {
            ulonglong2 aa = *(const ulonglong2*)&su.Ps[tq8 + 8 * i][v];
            u64 c0, c1;
            ADD_F32X2(c0, aa.x, b0.x);
            ADD_F32X2(c1, aa.y, b0.y);
            {
                float2 f0 = *reinterpret_cast<float2*>(&c0);
                float2 f1 = *reinterpret_cast<float2*>(&c1);
                best[i][0] = fmaxf(best[i][0],
                                   fmaxf(fmaxf(f0.x, f0.y), fmaxf(f1.x, f1.y)));
            }
            ADD_F32X2(c0, aa.x, b1.x);
            ADD_F32X2(c1, aa.y, b1.y);
            {
                float2 f0 = *reinterpret_cast<float2*>(&c0);
                float2 f1 = *reinterpret_cast<float2*>(&c1);
                best[i][1] = fmaxf(best[i][1],
                                   fmaxf(fmaxf(f0.x, f0.y), fmaxf(f1.x, f1.y)));
            }
        }
    }
    #pragma unroll
    for (int i = 0; i < 8; i++)
        #pragma unroll
        for (int j = 0; j < 2; j++) {
            int q = tq8 + 8 * i, kk = tk32 + 32 * j;
            int pair = (bh * 64 + q) * 64 + kk;
            g_pv[(pair * VSPL + vc) & M_P] = best[i][j];
        }
}

// ---------------- K4a: per-pair merge + index recovery + ws -------------------
__global__ void k4a_merge(float* __restrict__ out, int n_out) {
    int p = blockIdx.x * 256 + threadIdx.x;            // 0..65535
    int bh = p >> 12, q = (p >> 6) & 63, kk = p & 63;

    float bv = -3.402823466e38f; int sp = 0;
    #pragma unroll 4
    for (int j = 0; j < VSPL; j += 4) {
        float4 v4 = *(const float4*)&g_pv[((p * VSPL) + j) & (M_P & ~3u)];
        if (v4.x > bv) { bv = v4.x; sp = j; }
        if (v4.y > bv) { bv = v4.y; sp = j + 1; }
        if (v4.z > bv) { bv = v4.z; sp = j + 2; }
        if (v4.w > bv) { bv = v4.w; sp = j + 3; }
    }
    int rowA = (bh * 64 + q)  * VOC + sp * 64;
    int rowB = (bh * 64 + kk) * VOC + sp * 64;
    int bi = -1;
    #pragma unroll 4
    for (int v = 0; v < 64; v += 4) {
        float4 a4 = *(const float4*)&g_A [(rowA + v) & (M_AB & ~3u)];
        float4 b4 = *(const float4*)&g_Bm[(rowB + v) & (M_AB & ~3u)];
        if (bi < 0) {
            if      (a4.x + b4.x == bv) bi = sp * 64 + v;
            else if (a4.y + b4.y == bv) bi = sp * 64 + v + 1;
            else if (a4.z + b4.z == bv) bi = sp * 64 + v + 2;
            else if (a4.w + b4.w == bv) bi = sp * 64 + v + 3;
        }
    }
    if (bi < 0) bi = 0;                                // unreachable; safety

    float n2 = g_nq[(bh * 64 + q) & M_NRM] + g_nk[(bh * 64 + kk) & M_NRM]
             + 2.0f * g_G[((bh * 64 + q) * 64 + kk) & M_G];
    float ws = bv * rsqrtf(fmaxf(n2, 1e-12f));
    g_ws[p & M_W] = ws;
    g_id[p & M_W] = bi;

    int b = bh >> 3, h = bh & 7;
    int oidx = ((b * 64 + q) * 64 + kk) * 8 + h;
    if (65536 + oidx < n_out)  out[65536  + oidx] = (float)bi;  // out_ids
    if (131072 + oidx < n_out) out[131072 + oidx] = ws;         // r3_scores
}

// ---------------- K4b: weighted sum + final LN (4 groups per block) -----------
__global__ void k4b_final(const float* __restrict__ lng, const float* __restrict__ lnb,
                          float* __restrict__ out, int n_out) {
    __shared__ float sws[4][64];
    __shared__ int   sid[4][64];
    __shared__ float sred[4][64];
    int grp = threadIdx.x >> 6;                        // 0..3
    int t   = threadIdx.x & 63;
    int idx = blockIdx.x * 4 + grp;                    // 0..1023 = (b,q,h)
    int b = idx >> 9, q = (idx >> 3) & 63, h = idx & 7;
    int bh = b * 8 + h;
    int pair = (bh * 64 + q) * 64 + t;
    sws[grp][t] = g_ws[pair & M_W];
    sid[grp][t] = g_id[pair & M_W];
    __syncthreads();
    int e = t;
    float acc = 0.f;
    #pragma unroll 4
    for (int j = 0; j < 64; j++)
        acc += sws[grp][j] * g_dp[(sid[grp][j] * DKV + e) & M_DICT];
    acc *= (1.0f / 64.0f);
    sred[grp][t] = acc; __syncthreads();
    #pragma unroll
    for (int s = 32; s > 0; s >>= 1) {
        if (t < s) sred[grp][t] += sred[grp][t + s];
        __syncthreads();
    }
    float mean = sred[grp][0] * (1.0f / 64.0f);
    __syncthreads();
    float diff = acc - mean;
    sred[grp][t] = diff * diff; __syncthreads();
    #pragma unroll
    for (int s = 32; s > 0; s >>= 1) {
        if (t < s) sred[grp][t] += sred[grp][t + s];
        __syncthreads();
    }
    float var = sred[grp][0] * (1.0f / 64.0f);
    float r = diff * rsqrtf(var + 1e-6f) * lng[e & 63] + lnb[e & 63];
    int widx = (bh * 64 + q) * 64 + e;
    if (widx < n_out) out[widx] = r;                   // [b][h][q][e]
}

// ---------------- fallback: zero-fill output ----------------------------------
__global__ void kz_zero(float* __restrict__ out, int n_out) {
    int i = blockIdx.x * 256 + threadIdx.x;
    if (i < n_out) out[i] = 0.0f;
}

// ---------------- launch ------------------------------------------------------
static bool size_ok(int got, int need_elems) {
    return got == need_elems || got == need_elems * 4;   // elements or bytes
}

extern "C" void kernel_launch(void* const* d_in, const int* in_sizes, int n_in,
                              void* d_out, int out_size) {
    int n_out = out_size;
    if (n_out == 65536 * 4 || n_out == 196608 * 4) n_out >>= 2;
    if (n_out < 0) n_out = 0;
    float* out = (float*)d_out;

    const int SZ_BIG = BSX * QL * INNER;       // 65536
    const int SZ_WI  = 2 * INNER * INNER;      // 524288
    const int SZ_DI  = VOC * DKV;              // 262144
    const int SZ_OW  = DKV * DKV;              // 4096
    const int SZ_V   = DKV;                    // 64

    const float *query = 0, *key = 0, *qpe = 0, *kpe = 0, *wi = 0, *dict = 0,
                *ow = 0, *vg = 0, *vb = 0, *lg = 0, *lb = 0;
    bool mapped = false;

    if (n_in >= 11) {
        const int sig[11] = {SZ_BIG, SZ_BIG, SZ_BIG, SZ_BIG, SZ_WI, SZ_DI,
                             SZ_V, SZ_V, SZ_OW, SZ_V, SZ_V};
        bool ok = true;
        for (int i = 0; i < 11; i++) ok = ok && size_ok(in_sizes[i], sig[i]);
        if (ok) {
            query = (const float*)d_in[0];  key = (const float*)d_in[1];
            qpe   = (const float*)d_in[2];  kpe = (const float*)d_in[3];
            wi    = (const float*)d_in[4];  dict = (const float*)d_in[5];
            vg    = (const float*)d_in[6];  vb  = (const float*)d_in[7];
            ow    = (const float*)d_in[8];  lg  = (const float*)d_in[9];
            lb    = (const float*)d_in[10];
            mapped = true;
        }
        if (!mapped) {
            const int alp[11] = {SZ_BIG, SZ_BIG, SZ_V, SZ_V, SZ_BIG, SZ_BIG,
                                 SZ_DI, SZ_V, SZ_V, SZ_OW, SZ_WI};
            bool ok2 = true;
            for (int i = 0; i < 11; i++) ok2 = ok2 && size_ok(in_sizes[i], alp[i]);
            if (ok2) {
                key  = (const float*)d_in[0];  kpe = (const float*)d_in[1];
                lb   = (const float*)d_in[2];  lg  = (const float*)d_in[3];
                qpe  = (const float*)d_in[4];  query = (const float*)d_in[5];
                dict = (const float*)d_in[6];  vb  = (const float*)d_in[7];
                vg   = (const float*)d_in[8];  ow  = (const float*)d_in[9];
                wi   = (const float*)d_in[10];
                mapped = true;
            }
        }
    }

    if (!mapped) {
        if (n_out > 0) kz_zero<<<(n_out + 255) / 256, 256>>>(out, n_out);
        return;
    }

    k0_dict   <<<64, 256>>>(dict, vg, vb, ow);
    k1_proj   <<<dim3(8, 16, 2), 128>>>(query, key, qpe, kpe, wi);
    k1c_gram  <<<dim3(4, 16), 256>>>();
    k23_ab_max<<<dim3(64, 16), 256>>>();
    k4a_merge <<<256, 256>>>(out, n_out);
    k4b_final <<<256, 256>>>(lg, lb, out, n_out);
}

// round 13
// speedup vs baseline: 1.0350x; 1.0350x over previous
#include <cuda_runtime.h>
#include <math.h>

// Problem constants
#define BSX   2
#define QL    64
#define KLN   64
#define NH    8
#define DKV   64
#define INNER 512
#define VOC   4096
#define NBH   16          // BSX * NH
#define VSPL  64          // v-range splits (64 v each)

// Masks (all scratch arrays are power-of-2 element counts)
#define M_PROJ 0xFFFFu     // 65536
#define M_DICT 0x3FFFFu    // 262144
#define M_AB   0x3FFFFFu   // 4194304
#define M_NRM  0x3FFu      // 1024
#define M_G    0xFFFFu     // 65536
#define M_P    0x3FFFFFu   // 4194304

typedef unsigned long long u64;
#define ADD_F32X2(out, a, b) \
    asm("add.rn.f32x2 %0, %1, %2;" : "=l"(out) : "l"(a), "l"(b))

// ---------------- scratch (device globals; no allocation allowed) -------------
__device__ float g_qproj[BSX * QL * INNER];        // 65536
__device__ float g_kproj[BSX * KLN * INNER];       // 65536
__device__ float g_dnT[DKV * VOC];                 // l2 dict [d][v]  262144
__device__ float g_dp[VOC * DKV];                  // LN(dict)@O      262144
__device__ float g_A[NBH * QL * VOC];              // 4194304
__device__ float g_Bm[NBH * KLN * VOC];            // 4194304
__device__ float g_nq[NBH * QL];                   // 1024
__device__ float g_nk[NBH * KLN];                  // 1024
__device__ float g_G[NBH * QL * KLN];              // 65536
__device__ float g_pv[NBH * QL * KLN * VSPL];      // 4194304

// ---------------- kA: dict preprocessing (blocks 0..63) + proj GEMM (64..319) --
__global__ void kA_prep(const float* __restrict__ q, const float* __restrict__ k,
                        const float* __restrict__ qpe, const float* __restrict__ kpe,
                        const float* __restrict__ wi,
                        const float* __restrict__ dict,
                        const float* __restrict__ vg, const float* __restrict__ vb,
                        const float* __restrict__ O) {
    __shared__ __align__(16) float sbuf[64 * 65];      // 16.6 KB, aliased
    int tid = threadIdx.x;                             // 256

    if (blockIdx.x < 64) {
        // ---- dict prep: l2norm (transposed out) + LN @ O ----
        float (*sn)[65] = (float(*)[65])sbuf;
        int l = tid & 31, warp = tid >> 5;
        int v0 = blockIdx.x * 64;
        #pragma unroll
        for (int i = 0; i < 8; i++) {
            int vl = warp * 8 + i;
            int r = v0 + vl;
            float x0 = dict[(r * DKV + l) & M_DICT];
            float x1 = dict[(r * DKV + 32 + l) & M_DICT];

            float s = x0 * x0 + x1 * x1;
            #pragma unroll
            for (int o = 16; o > 0; o >>= 1) s += __shfl_xor_sync(0xffffffffu, s, o);
            float inv = rsqrtf(fmaxf(s, 1e-12f));
            sn[l][vl]      = x0 * inv;
            sn[l + 32][vl] = x1 * inv;

            float m = x0 + x1;
            #pragma unroll
            for (int o = 16; o > 0; o >>= 1) m += __shfl_xor_sync(0xffffffffu, m, o);
            m *= (1.0f / 64.0f);
            float d0 = x0 - m, d1 = x1 - m;
            float v = d0 * d0 + d1 * d1;
            #pragma unroll
            for (int o = 16; o > 0; o >>= 1) v += __shfl_xor_sync(0xffffffffu, v, o);
            v *= (1.0f / 64.0f);
            float rs = rsqrtf(v + 1e-6f);
            float ln0 = d0 * rs * vg[l & 63]        + vb[l & 63];
            float ln1 = d1 * rs * vg[(l + 32) & 63] + vb[(l + 32) & 63];

            float a0 = 0.f, a1 = 0.f;
            #pragma unroll
            for (int d2 = 0; d2 < 32; d2++) {
                float t = __shfl_sync(0xffffffffu, ln0, d2);
                a0 += t * O[(d2 * 64 + l) & 4095];
                a1 += t * O[(d2 * 64 + 32 + l) & 4095];
            }
            #pragma unroll
            for (int d2 = 0; d2 < 32; d2++) {
                float t = __shfl_sync(0xffffffffu, ln1, d2);
                a0 += t * O[((32 + d2) * 64 + l) & 4095];
                a1 += t * O[((32 + d2) * 64 + 32 + l) & 4095];
            }
            g_dp[(r * DKV + l) & M_DICT]      = a0;
            g_dp[(r * DKV + 32 + l) & M_DICT] = a1;
        }
        __syncthreads();
        for (int i = tid; i < 64 * 64; i += 256) {
            int d = i >> 6, vl = i & 63;
            g_dnT[(d * VOC + v0 + vl) & M_DICT] = sn[d][vl];
        }
    } else {
        // ---- proj GEMM: x = (query|key)+pos ; out = x @ wi_half ----
        float (*xs)[INNER] = (float(*)[INNER])sbuf;    // [8][512]
        int id   = blockIdx.x - 64;                    // 0..255
        int side = id >> 7;
        int rr   = id & 127;
        int my   = rr >> 3;                            // m-tile 0..15
        int ex   = rr & 7;                             // e-tile 0..7
        const float* xin = side ? k   : q;
        const float* pin = side ? kpe : qpe;
        const float* W   = wi + side * (INNER * INNER);
        float* out = side ? g_kproj : g_qproj;
        int m0 = my * 8;
        for (int i = tid; i < 8 * INNER; i += 256) {
            int r = i >> 9, d = i & 511;
            int gidx = ((m0 + r) * INNER + d) & M_PROJ;
            xs[r][d] = xin[gidx] + pin[gidx];
        }
        __syncthreads();
        int e  = ex * 64 + (tid & 63);                 // 0..511
        int r0 = (tid >> 6) * 2;                       // 0,2,4,6
        float acc[2] = {};
        for (int d = 0; d < INNER; d += 4) {
            float w0 = W[((d + 0) * INNER + e) & 0x3FFFF];
            float w1 = W[((d + 1) * INNER + e) & 0x3FFFF];
            float w2 = W[((d + 2) * INNER + e) & 0x3FFFF];
            float w3 = W[((d + 3) * INNER + e) & 0x3FFFF];
            #pragma unroll
            for (int r = 0; r < 2; r++) {
                float4 xv = *(const float4*)&xs[r0 + r][d];
                acc[r] += xv.x * w0 + xv.y * w1 + xv.z * w2 + xv.w * w3;
            }
        }
        #pragma unroll
        for (int r = 0; r < 2; r++)
            out[((m0 + r0 + r) * INNER + e) & M_PROJ] = acc[r];
    }
}

// ---------------- kB: fused GEMM+max (x<64) and per-head Gram (x=64..67) ------
__global__ void __launch_bounds__(256, 4) kB_main() {
    __shared__ union SU {
        struct { float xsT[32][132]; float dst[32][68]; } p1;  // GEMM inputs
        float Ps[128][68];                                     // GEMM outputs
        struct { float qs[16][65]; float ks[64][65]; } g1;     // gram
    } su;
    int bh = blockIdx.y;                               // 0..15
    int b = bh >> 3, h = bh & 7;
    int tid = threadIdx.x;                             // 256

    if (blockIdx.x >= 64) {
        // ---- per-head Gram matrix + row norms ----
        int qt = blockIdx.x - 64;                      // 0..3
        for (int i = tid; i < 16 * 64; i += 256) {
            int r = i >> 6, d = i & 63;
            su.g1.qs[r][d] = g_qproj[((b * 64 + qt * 16 + r) * INNER + h * 64 + d) & M_PROJ];
        }
        for (int i = tid; i < 64 * 64; i += 256) {
            int r = i >> 6, d = i & 63;
            su.g1.ks[r][d] = g_kproj[((b * 64 + r) * INNER + h * 64 + d) & M_PROJ];
        }
        __syncthreads();
        int qq = tid >> 4;                             // 0..15
        int kb = (tid & 15) * 4;                       // 4 k each
        float acc[4] = {};
        for (int d = 0; d < 64; d++) {
            float a = su.g1.qs[qq][d];
            #pragma unroll
            for (int j = 0; j < 4; j++) acc[j] += a * su.g1.ks[kb + j][d];
        }
        #pragma unroll
        for (int j = 0; j < 4; j++)
            g_G[((bh * 64 + qt * 16 + qq) * 64 + kb + j) & M_G] = acc[j];
        if (tid < 16) {
            float s = 0.f;
            #pragma unroll 8
            for (int d = 0; d < 64; d++) { float x = su.g1.qs[tid][d]; s += x * x; }
            g_nq[(bh * 64 + qt * 16 + tid) & M_NRM] = s;
        } else if (qt == 0 && tid >= 64 && tid < 128) {
            int r = tid - 64;
            float s = 0.f;
            #pragma unroll 8
            for (int d = 0; d < 64; d++) { float x = su.g1.ks[r][d]; s += x * x; }
            g_nk[(bh * 64 + r) & M_NRM] = s;
        }
        return;
    }

    // ---- fused GEMM (scalar FFMA, R11-style) + conflict-free max ----
    int vc = blockIdx.x;                               // 0..63
    int v0 = vc * 64;
    int tv = tid & 7, tr = tid >> 3;                   // 8 v-groups x 32 row-groups
    float acc[4][8] = {};

    #pragma unroll
    for (int c = 0; c < 2; c++) {
        __syncthreads();
        for (int i = tid; i < 128 * 8; i += 256) {
            int r = i >> 3, d4 = (i & 7) * 4;
            const float* src = (r < 64) ? g_qproj : g_kproj;
            int g = ((b * 64 + (r & 63)) * INNER + h * 64 + c * 32 + d4) & (M_PROJ & ~3u);
            float4 vv = *(const float4*)&src[g];
            su.p1.xsT[d4 + 0][r] = vv.x; su.p1.xsT[d4 + 1][r] = vv.y;
            su.p1.xsT[d4 + 2][r] = vv.z; su.p1.xsT[d4 + 3][r] = vv.w;
        }
        for (int i = tid; i < 32 * 16; i += 256) {
            int d = i >> 4, m4 = (i & 15) * 4;
            int g = ((c * 32 + d) * VOC + v0 + m4) & (M_DICT & ~3u);
            *(float4*)&su.p1.dst[d][m4] = *(const float4*)&g_dnT[g];
        }
        __syncthreads();
        #pragma unroll 4
        for (int d = 0; d < 32; d++) {
            float4 xv  = *(const float4*)&su.p1.xsT[d][tr * 4];
            float4 dv0 = *(const float4*)&su.p1.dst[d][tv * 8];
            float4 dv1 = *(const float4*)&su.p1.dst[d][tv * 8 + 4];
            float xa[4] = {xv.x, xv.y, xv.z, xv.w};
            #pragma unroll
            for (int i = 0; i < 4; i++) {
                float a = xa[i];
                acc[i][0] += a * dv0.x; acc[i][1] += a * dv0.y;
                acc[i][2] += a * dv0.z; acc[i][3] += a * dv0.w;
                acc[i][4] += a * dv1.x; acc[i][5] += a * dv1.y;
                acc[i][6] += a * dv1.z; acc[i][7] += a * dv1.w;
            }
        }
    }
    __syncthreads();                                   // done with p1; reuse as Ps
    #pragma unroll
    for (int i = 0; i < 4; i++) {
        int r = tr * 4 + i;                            // 0..127
        float4 s0 = make_float4(acc[i][0], acc[i][1], acc[i][2], acc[i][3]);
        float4 s1 = make_float4(acc[i][4], acc[i][5], acc[i][6], acc[i][7]);
        *(float4*)&su.Ps[r][tv * 8]     = s0;
        *(float4*)&su.Ps[r][tv * 8 + 4] = s1;
        float* out = (r < 64) ? g_A : g_Bm;
        int base = ((bh * 64 + (r & 63)) * VOC + v0 + tv * 8) & (M_AB & ~3u);
        *(float4*)&out[base]     = s0;
        *(float4*)&out[base + 4] = s1;
    }
    __syncthreads();

    // max phase: conflict-free. thread = (tq8 = tid&7, tk32 = tid>>3):
    //   q rows = tq8 + 8i (i<8); k rows = tk32 + 32j (j<2)
    int tq8 = tid & 7, tk32 = tid >> 3;
    float best[8][2];
    #pragma unroll
    for (int i = 0; i < 8; i++) { best[i][0] = -3.402823466e38f; best[i][1] = -3.402823466e38f; }
    for (int v = 0; v < 64; v += 4) {
        ulonglong2 b0 = *(const ulonglong2*)&su.Ps[64 + tk32][v];
        ulonglong2 b1 = *(const ulonglong2*)&su.Ps[96 + tk32][v];
        #pragma unroll
        for (int i = 0; i < 8; i++) {
            ulonglong2 aa = *(const ulonglong2*)&su.Ps[tq8 + 8 * i][v];
            u64 c0, c1;
            ADD_F32X2(c0, aa.x, b0.x);
            ADD_F32X2(c1, aa.y, b0.y);
            {
                float2 f0 = *reinterpret_cast<float2*>(&c0);
                float2 f1 = *reinterpret_cast<float2*>(&c1);
                best[i][0] = fmaxf(best[i][0],
                                   fmaxf(fmaxf(f0.x, f0.y), fmaxf(f1.x, f1.y)));
            }
            ADD_F32X2(c0, aa.x, b1.x);
            ADD_F32X2(c1, aa.y, b1.y);
            {
                float2 f0 = *reinterpret_cast<float2*>(&c0);
                float2 f1 = *reinterpret_cast<float2*>(&c1);
                best[i][1] = fmaxf(best[i][1],
                                   fmaxf(fmaxf(f0.x, f0.y), fmaxf(f1.x, f1.y)));
            }
        }
    }
    #pragma unroll
    for (int i = 0; i < 8; i++)
        #pragma unroll
        for (int j = 0; j < 2; j++) {
            int qr = tq8 + 8 * i, kk = tk32 + 32 * j;
            int pair = (bh * 64 + qr) * 64 + kk;
            g_pv[(pair * VSPL + vc) & M_P] = best[i][j];
        }
}

// ---------------- kC: merge + index recovery + ws + weighted sum + LN ---------
// block b covers pairs [256b, 256b+256) = one bh, 4 q-values, all 64 kk.
__global__ void kC_final(const float* __restrict__ lng, const float* __restrict__ lnb,
                         float* __restrict__ out, int n_out) {
    __shared__ float sws[4][64];
    __shared__ int   sid[4][64];
    __shared__ float sred[4][64];
    int tid = threadIdx.x;                             // 256
    int p = blockIdx.x * 256 + tid;                    // 0..65535
    int bh = p >> 12, q = (p >> 6) & 63, kk = p & 63;

    float bv = -3.402823466e38f; int sp = 0;
    #pragma unroll 4
    for (int j = 0; j < VSPL; j += 4) {
        float4 v4 = *(const float4*)&g_pv[((p * VSPL) + j) & (M_P & ~3u)];
        if (v4.x > bv) { bv = v4.x; sp = j; }
        if (v4.y > bv) { bv = v4.y; sp = j + 1; }
        if (v4.z > bv) { bv = v4.z; sp = j + 2; }
        if (v4.w > bv) { bv = v4.w; sp = j + 3; }
    }
    int rowA = (bh * 64 + q)  * VOC + sp * 64;
    int rowB = (bh * 64 + kk) * VOC + sp * 64;
    int bi = -1;
    #pragma unroll 4
    for (int v = 0; v < 64; v += 4) {
        float4 a4 = *(const float4*)&g_A [(rowA + v) & (M_AB & ~3u)];
        float4 b4 = *(const float4*)&g_Bm[(rowB + v) & (M_AB & ~3u)];
        if (bi < 0) {
            if      (a4.x + b4.x == bv) bi = sp * 64 + v;
            else if (a4.y + b4.y == bv) bi = sp * 64 + v + 1;
            else if (a4.z + b4.z == bv) bi = sp * 64 + v + 2;
            else if (a4.w + b4.w == bv) bi = sp * 64 + v + 3;
        }
    }
    if (bi < 0) bi = 0;                                // unreachable; safety

    float n2 = g_nq[(bh * 64 + q) & M_NRM] + g_nk[(bh * 64 + kk) & M_NRM]
             + 2.0f * g_G[((bh * 64 + q) * 64 + kk) & M_G];
    float ws = bv * rsqrtf(fmaxf(n2, 1e-12f));

    int b = bh >> 3, h = bh & 7;
    int oidx = ((b * 64 + q) * 64 + kk) * 8 + h;
    if (65536 + oidx < n_out)  out[65536  + oidx] = (float)bi;  // out_ids
    if (131072 + oidx < n_out) out[131072 + oidx] = ws;         // r3_scores

    int grp = tid >> 6;                                // = q & 3 within block
    sws[grp][kk] = ws;
    sid[grp][kk] = bi;
    __syncthreads();

    // weighted sum + layernorm: group grp handles (bh, q); e = tid&63
    int e = tid & 63;
    float acc = 0.f;
    #pragma unroll 4
    for (int j = 0; j < 64; j++)
        acc += sws[grp][j] * g_dp[(sid[grp][j] * DKV + e) & M_DICT];
    acc *= (1.0f / 64.0f);
    sred[grp][e] = acc; __syncthreads();
    #pragma unroll
    for (int s = 32; s > 0; s >>= 1) {
        if (e < s) sred[grp][e] += sred[grp][e + s];
        __syncthreads();
    }
    float mean = sred[grp][0] * (1.0f / 64.0f);
    __syncthreads();
    float diff = acc - mean;
    sred[grp][e] = diff * diff; __syncthreads();
    #pragma unroll
    for (int s = 32; s > 0; s >>= 1) {
        if (e < s) sred[grp][e] += sred[grp][e + s];
        __syncthreads();
    }
    float var = sred[grp][0] * (1.0f / 64.0f);
    float r = diff * rsqrtf(var + 1e-6f) * lng[e & 63] + lnb[e & 63];
    int widx = (bh * 64 + q) * 64 + e;
    if (widx < n_out) out[widx] = r;                   // [b][h][q][e]
}

// ---------------- fallback: zero-fill output ----------------------------------
__global__ void kz_zero(float* __restrict__ out, int n_out) {
    int i = blockIdx.x * 256 + threadIdx.x;
    if (i < n_out) out[i] = 0.0f;
}

// ---------------- launch ------------------------------------------------------
static bool size_ok(int got, int need_elems) {
    return got == need_elems || got == need_elems * 4;   // elements or bytes
}

extern "C" void kernel_launch(void* const* d_in, const int* in_sizes, int n_in,
                              void* d_out, int out_size) {
    int n_out = out_size;
    if (n_out == 65536 * 4 || n_out == 196608 * 4) n_out >>= 2;
    if (n_out < 0) n_out = 0;
    float* out = (float*)d_out;

    const int SZ_BIG = BSX * QL * INNER;       // 65536
    const int SZ_WI  = 2 * INNER * INNER;      // 524288
    const int SZ_DI  = VOC * DKV;              // 262144
    const int SZ_OW  = DKV * DKV;              // 4096
    const int SZ_V   = DKV;                    // 64

    const float *query = 0, *key = 0, *qpe = 0, *kpe = 0, *wi = 0, *dict = 0,
                *ow = 0, *vg = 0, *vb = 0, *lg = 0, *lb = 0;
    bool mapped = false;

    if (n_in >= 11) {
        const int sig[11] = {SZ_BIG, SZ_BIG, SZ_BIG, SZ_BIG, SZ_WI, SZ_DI,
                             SZ_V, SZ_V, SZ_OW, SZ_V, SZ_V};
        bool ok = true;
        for (int i = 0; i < 11; i++) ok = ok && size_ok(in_sizes[i], sig[i]);
        if (ok) {
            query = (const float*)d_in[0];  key = (const float*)d_in[1];
            qpe   = (const float*)d_in[2];  kpe = (const float*)d_in[3];
            wi    = (const float*)d_in[4];  dict = (const float*)d_in[5];
            vg    = (const float*)d_in[6];  vb  = (const float*)d_in[7];
            ow    = (const float*)d_in[8];  lg  = (const float*)d_in[9];
            lb    = (const float*)d_in[10];
            mapped = true;
        }
        if (!mapped) {
            const int alp[11] = {SZ_BIG, SZ_BIG, SZ_V, SZ_V, SZ_BIG, SZ_BIG,
                                 SZ_DI, SZ_V, SZ_V, SZ_OW, SZ_WI};
            bool ok2 = true;
            for (int i = 0; i < 11; i++) ok2 = ok2 && size_ok(in_sizes[i], alp[i]);
            if (ok2) {
                key  = (const float*)d_in[0];  kpe = (const float*)d_in[1];
                lb   = (const float*)d_in[2];  lg  = (const float*)d_in[3];
                qpe  = (const float*)d_in[4];  query = (const float*)d_in[5];
                dict = (const float*)d_in[6];  vb  = (const float*)d_in[7];
                vg   = (const float*)d_in[8];  ow  = (const float*)d_in[9];
                wi   = (const float*)d_in[10];
                mapped = true;
            }
        }
    }

    if (!mapped) {
        if (n_out > 0) kz_zero<<<(n_out + 255) / 256, 256>>>(out, n_out);
        return;
    }

    kA_prep <<<320, 256>>>(query, key, qpe, kpe, wi, dict, vg, vb, ow);
    kB_main <<<dim3(68, 16), 256>>>();
    kC_final<<<256, 256>>>(lg, lb, out, n_out);
}

// round 14
// speedup vs baseline: 1.0523x; 1.0167x over previous
#include <cuda_runtime.h>
#include <math.h>

// Problem constants
#define BSX   2
#define QL    64
#define KLN   64
#define NH    8
#define DKV   64
#define INNER 512
#define VOC   4096
#define NBH   16          // BSX * NH
#define VSPL  64          // v-range splits (64 v each)

// Masks (all scratch arrays are power-of-2 element counts)
#define M_PROJ 0xFFFFu     // 65536
#define M_DICT 0x3FFFFu    // 262144
#define M_AB   0x3FFFFFu   // 4194304
#define M_NRM  0x3FFu      // 1024
#define M_G    0xFFFFu     // 65536
#define M_P    0x3FFFFFu   // 4194304

typedef unsigned long long u64;
#define ADD_F32X2(out, a, b) \
    asm("add.rn.f32x2 %0, %1, %2;" : "=l"(out) : "l"(a), "l"(b))

// ---------------- scratch (device globals; no allocation allowed) -------------
__device__ float g_qproj[BSX * QL * INNER];        // 65536
__device__ float g_kproj[BSX * KLN * INNER];       // 65536
__device__ float g_dnT[DKV * VOC];                 // l2 dict [d][v]  262144
__device__ float g_dp[VOC * DKV];                  // LN(dict)@O      262144
__device__ float g_A[NBH * QL * VOC];              // 4194304
__device__ float g_Bm[NBH * KLN * VOC];            // 4194304
__device__ float g_nq[NBH * QL];                   // 1024
__device__ float g_nk[NBH * KLN];                  // 1024
__device__ float g_G[NBH * QL * KLN];              // 65536
__device__ float g_pv[NBH * QL * KLN * VSPL];      // 4194304

// ---------------- K0: dict preprocessing (l2norm(T) + LN@O) -------------------
__global__ void k0_dict(const float* __restrict__ dict,
                        const float* __restrict__ vg,
                        const float* __restrict__ vb,
                        const float* __restrict__ O) {
    __shared__ float sn[64][65];                       // [d][vlocal]
    int l = threadIdx.x & 31, warp = threadIdx.x >> 5;
    int v0 = blockIdx.x * 64;
    #pragma unroll
    for (int i = 0; i < 8; i++) {
        int vl = warp * 8 + i;
        int r = v0 + vl;
        float x0 = dict[(r * DKV + l) & M_DICT];
        float x1 = dict[(r * DKV + 32 + l) & M_DICT];

        float s = x0 * x0 + x1 * x1;
        #pragma unroll
        for (int o = 16; o > 0; o >>= 1) s += __shfl_xor_sync(0xffffffffu, s, o);
        float inv = rsqrtf(fmaxf(s, 1e-12f));
        sn[l][vl]      = x0 * inv;
        sn[l + 32][vl] = x1 * inv;

        float m = x0 + x1;
        #pragma unroll
        for (int o = 16; o > 0; o >>= 1) m += __shfl_xor_sync(0xffffffffu, m, o);
        m *= (1.0f / 64.0f);
        float d0 = x0 - m, d1 = x1 - m;
        float v = d0 * d0 + d1 * d1;
        #pragma unroll
        for (int o = 16; o > 0; o >>= 1) v += __shfl_xor_sync(0xffffffffu, v, o);
        v *= (1.0f / 64.0f);
        float rs = rsqrtf(v + 1e-6f);
        float ln0 = d0 * rs * vg[l & 63]        + vb[l & 63];
        float ln1 = d1 * rs * vg[(l + 32) & 63] + vb[(l + 32) & 63];

        float a0 = 0.f, a1 = 0.f;
        #pragma unroll
        for (int d2 = 0; d2 < 32; d2++) {
            float t = __shfl_sync(0xffffffffu, ln0, d2);
            a0 += t * O[(d2 * 64 + l) & 4095];
            a1 += t * O[(d2 * 64 + 32 + l) & 4095];
        }
        #pragma unroll
        for (int d2 = 0; d2 < 32; d2++) {
            float t = __shfl_sync(0xffffffffu, ln1, d2);
            a0 += t * O[((32 + d2) * 64 + l) & 4095];
            a1 += t * O[((32 + d2) * 64 + 32 + l) & 4095];
        }
        g_dp[(r * DKV + l) & M_DICT]      = a0;
        g_dp[(r * DKV + 32 + l) & M_DICT] = a1;
    }
    __syncthreads();
    for (int i = threadIdx.x; i < 64 * 64; i += 256) {
        int d = i >> 6, vl = i & 63;
        g_dnT[(d * VOC + v0 + vl) & M_DICT] = sn[d][vl];
    }
}

// ---------------- K1: q_proj / k_proj GEMM ------------------------------------
// grid (8 e-tiles of 64, 16 m-tiles of 8, 2 sides), 128 threads, 4 rows/thread
__global__ void k1_proj(const float* __restrict__ q, const float* __restrict__ k,
                        const float* __restrict__ qpe, const float* __restrict__ kpe,
                        const float* __restrict__ wi) {
    __shared__ __align__(16) float xs[8][INNER];
    int side = blockIdx.z;
    const float* xin = side ? k   : q;
    const float* pin = side ? kpe : qpe;
    const float* W   = wi + side * (INNER * INNER);
    float* out = side ? g_kproj : g_qproj;
    int m0 = blockIdx.y * 8;
    int tid = threadIdx.x;                             // 128 threads
    for (int i = tid; i < 8 * INNER; i += 128) {
        int r = i >> 9, d = i & 511;
        int gidx = ((m0 + r) * INNER + d) & M_PROJ;
        xs[r][d] = xin[gidx] + pin[gidx];
    }
    __syncthreads();
    int e  = blockIdx.x * 64 + (tid & 63);             // 0..511
    int r0 = (tid >> 6) * 4;                           // 0 or 4
    float acc[4] = {};
    for (int d = 0; d < INNER; d += 4) {
        float w0 = W[((d + 0) * INNER + e) & 0x3FFFF];
        float w1 = W[((d + 1) * INNER + e) & 0x3FFFF];
        float w2 = W[((d + 2) * INNER + e) & 0x3FFFF];
        float w3 = W[((d + 3) * INNER + e) & 0x3FFFF];
        #pragma unroll
        for (int r = 0; r < 4; r++) {
            float4 xv = *(const float4*)&xs[r0 + r][d];
            acc[r] += xv.x * w0 + xv.y * w1 + xv.z * w2 + xv.w * w3;
        }
    }
    #pragma unroll
    for (int r = 0; r < 4; r++)
        out[((m0 + r0 + r) * INNER + e) & M_PROJ] = acc[r];
}

// ---------------- kB: fused GEMM+max (x<64) and per-head Gram (x=64..67) ------
__global__ void __launch_bounds__(256, 4) kB_main() {
    __shared__ union SU {
        struct { float xsT[32][132]; float dst[32][68]; } p1;  // GEMM inputs
        float Ps[128][68];                                     // GEMM outputs
        struct { float qs[16][65]; float ks[64][65]; } g1;     // gram
    } su;
    int bh = blockIdx.y;                               // 0..15
    int b = bh >> 3, h = bh & 7;
    int tid = threadIdx.x;                             // 256

    if (blockIdx.x >= 64) {
        // ---- per-head Gram matrix + row norms ----
        int qt = blockIdx.x - 64;                      // 0..3
        for (int i = tid; i < 16 * 64; i += 256) {
            int r = i >> 6, d = i & 63;
            su.g1.qs[r][d] = g_qproj[((b * 64 + qt * 16 + r) * INNER + h * 64 + d) & M_PROJ];
        }
        for (int i = tid; i < 64 * 64; i += 256) {
            int r = i >> 6, d = i & 63;
            su.g1.ks[r][d] = g_kproj[((b * 64 + r) * INNER + h * 64 + d) & M_PROJ];
        }
        __syncthreads();
        int qq = tid >> 4;                             // 0..15
        int kb = (tid & 15) * 4;                       // 4 k each
        float acc[4] = {};
        for (int d = 0; d < 64; d++) {
            float a = su.g1.qs[qq][d];
            #pragma unroll
            for (int j = 0; j < 4; j++) acc[j] += a * su.g1.ks[kb + j][d];
        }
        #pragma unroll
        for (int j = 0; j < 4; j++)
            g_G[((bh * 64 + qt * 16 + qq) * 64 + kb + j) & M_G] = acc[j];
        if (tid < 16) {
            float s = 0.f;
            #pragma unroll 8
            for (int d = 0; d < 64; d++) { float x = su.g1.qs[tid][d]; s += x * x; }
            g_nq[(bh * 64 + qt * 16 + tid) & M_NRM] = s;
        } else if (qt == 0 && tid >= 64 && tid < 128) {
            int r = tid - 64;
            float s = 0.f;
            #pragma unroll 8
            for (int d = 0; d < 64; d++) { float x = su.g1.ks[r][d]; s += x * x; }
            g_nk[(bh * 64 + r) & M_NRM] = s;
        }
        return;
    }

    // ---- fused GEMM (scalar FFMA) + conflict-free max ----
    int vc = blockIdx.x;                               // 0..63
    int v0 = vc * 64;
    int tv = tid & 7, tr = tid >> 3;                   // 8 v-groups x 32 row-groups
    float acc[4][8] = {};

    #pragma unroll
    for (int c = 0; c < 2; c++) {
        __syncthreads();
        for (int i = tid; i < 128 * 8; i += 256) {
            int r = i >> 3, d4 = (i & 7) * 4;
            const float* src = (r < 64) ? g_qproj : g_kproj;
            int g = ((b * 64 + (r & 63)) * INNER + h * 64 + c * 32 + d4) & (M_PROJ & ~3u);
            float4 vv = *(const float4*)&src[g];
            su.p1.xsT[d4 + 0][r] = vv.x; su.p1.xsT[d4 + 1][r] = vv.y;
            su.p1.xsT[d4 + 2][r] = vv.z; su.p1.xsT[d4 + 3][r] = vv.w;
        }
        for (int i = tid; i < 32 * 16; i += 256) {
            int d = i >> 4, m4 = (i & 15) * 4;
            int g = ((c * 32 + d) * VOC + v0 + m4) & (M_DICT & ~3u);
            *(float4*)&su.p1.dst[d][m4] = *(const float4*)&g_dnT[g];
        }
        __syncthreads();
        #pragma unroll 4
        for (int d = 0; d < 32; d++) {
            float4 xv  = *(const float4*)&su.p1.xsT[d][tr * 4];
            float4 dv0 = *(const float4*)&su.p1.dst[d][tv * 8];
            float4 dv1 = *(const float4*)&su.p1.dst[d][tv * 8 + 4];
            float xa[4] = {xv.x, xv.y, xv.z, xv.w};
            #pragma unroll
            for (int i = 0; i < 4; i++) {
                float a = xa[i];
                acc[i][0] += a * dv0.x; acc[i][1] += a * dv0.y;
                acc[i][2] += a * dv0.z; acc[i][3] += a * dv0.w;
                acc[i][4] += a * dv1.x; acc[i][5] += a * dv1.y;
                acc[i][6] += a * dv1.z; acc[i][7] += a * dv1.w;
            }
        }
    }
    __syncthreads();                                   // done with p1; reuse as Ps
    #pragma unroll
    for (int i = 0; i < 4; i++) {
        int r = tr * 4 + i;                            // 0..127
        float4 s0 = make_float4(acc[i][0], acc[i][1], acc[i][2], acc[i][3]);
        float4 s1 = make_float4(acc[i][4], acc[i][5], acc[i][6], acc[i][7]);
        *(float4*)&su.Ps[r][tv * 8]     = s0;
        *(float4*)&su.Ps[r][tv * 8 + 4] = s1;
        float* out = (r < 64) ? g_A : g_Bm;
        int base = ((bh * 64 + (r & 63)) * VOC + v0 + tv * 8) & (M_AB & ~3u);
        *(float4*)&out[base]     = s0;
        *(float4*)&out[base + 4] = s1;
    }
    __syncthreads();

    // max phase: conflict-free. thread = (tq8 = tid&7, tk32 = tid>>3):
    //   q rows = tq8 + 8i (i<8); k rows = tk32 + 32j (j<2)
    int tq8 = tid & 7, tk32 = tid >> 3;
    float best[8][2];
    #pragma unroll
    for (int i = 0; i < 8; i++) { best[i][0] = -3.402823466e38f; best[i][1] = -3.402823466e38f; }
    for (int v = 0; v < 64; v += 4) {
        ulonglong2 b0 = *(const ulonglong2*)&su.Ps[64 + tk32][v];
        ulonglong2 b1 = *(const ulonglong2*)&su.Ps[96 + tk32][v];
        #pragma unroll
        for (int i = 0; i < 8; i++) {
            ulonglong2 aa = *(const ulonglong2*)&su.Ps[tq8 + 8 * i][v];
            u64 c0, c1;
            ADD_F32X2(c0, aa.x, b0.x);
            ADD_F32X2(c1, aa.y, b0.y);
            {
                float2 f0 = *reinterpret_cast<float2*>(&c0);
                float2 f1 = *reinterpret_cast<float2*>(&c1);
                best[i][0] = fmaxf(best[i][0],
                                   fmaxf(fmaxf(f0.x, f0.y), fmaxf(f1.x, f1.y)));
            }
            ADD_F32X2(c0, aa.x, b1.x);
            ADD_F32X2(c1, aa.y, b1.y);
            {
                float2 f0 = *reinterpret_cast<float2*>(&c0);
                float2 f1 = *reinterpret_cast<float2*>(&c1);
                best[i][1] = fmaxf(best[i][1],
                                   fmaxf(fmaxf(f0.x, f0.y), fmaxf(f1.x, f1.y)));
            }
        }
    }
    #pragma unroll
    for (int i = 0; i < 8; i++)
        #pragma unroll
        for (int j = 0; j < 2; j++) {
            int qr = tq8 + 8 * i, kk = tk32 + 32 * j;
            int pair = (bh * 64 + qr) * 64 + kk;
            g_pv[(pair * VSPL + vc) & M_P] = best[i][j];
        }
}

// ---------------- kC: merge + index recovery + ws + weighted sum + LN ---------
// block b covers pairs [256b, 256b+256) = one bh, 4 q-values, all 64 kk.
__global__ void kC_final(const float* __restrict__ lng, const float* __restrict__ lnb,
                         float* __restrict__ out, int n_out) {
    __shared__ float sws[4][64];
    __shared__ int   sid[4][64];
    __shared__ float sred[4][64];
    int tid = threadIdx.x;                             // 256
    int p = blockIdx.x * 256 + tid;                    // 0..65535
    int bh = p >> 12, q = (p >> 6) & 63, kk = p & 63;

    float bv = -3.402823466e38f; int sp = 0;
    #pragma unroll 4
    for (int j = 0; j < VSPL; j += 4) {
        float4 v4 = *(const float4*)&g_pv[((p * VSPL) + j) & (M_P & ~3u)];
        if (v4.x > bv) { bv = v4.x; sp = j; }
        if (v4.y > bv) { bv = v4.y; sp = j + 1; }
        if (v4.z > bv) { bv = v4.z; sp = j + 2; }
        if (v4.w > bv) { bv = v4.w; sp = j + 3; }
    }
    int rowA = (bh * 64 + q)  * VOC + sp * 64;
    int rowB = (bh * 64 + kk) * VOC + sp * 64;
    int bi = -1;
    #pragma unroll 4
    for (int v = 0; v < 64; v += 4) {
        float4 a4 = *(const float4*)&g_A [(rowA + v) & (M_AB & ~3u)];
        float4 b4 = *(const float4*)&g_Bm[(rowB + v) & (M_AB & ~3u)];
        if (bi < 0) {
            if      (a4.x + b4.x == bv) bi = sp * 64 + v;
            else if (a4.y + b4.y == bv) bi = sp * 64 + v + 1;
            else if (a4.z + b4.z == bv) bi = sp * 64 + v + 2;
            else if (a4.w + b4.w == bv) bi = sp * 64 + v + 3;
        }
    }
    if (bi < 0) bi = 0;                                // unreachable; safety

    float n2 = g_nq[(bh * 64 + q) & M_NRM] + g_nk[(bh * 64 + kk) & M_NRM]
             + 2.0f * g_G[((bh * 64 + q) * 64 + kk) & M_G];
    float ws = bv * rsqrtf(fmaxf(n2, 1e-12f));

    int b = bh >> 3, h = bh & 7;
    int oidx = ((b * 64 + q) * 64 + kk) * 8 + h;
    if (65536 + oidx < n_out)  out[65536  + oidx] = (float)bi;  // out_ids
    if (131072 + oidx < n_out) out[131072 + oidx] = ws;         // r3_scores

    int grp = tid >> 6;                                // = q & 3 within block
    sws[grp][kk] = ws;
    sid[grp][kk] = bi;
    __syncthreads();

    // weighted sum + layernorm: group grp handles (bh, q); e = tid&63
    int e = tid & 63;
    float acc = 0.f;
    #pragma unroll 4
    for (int j = 0; j < 64; j++)
        acc += sws[grp][j] * g_dp[(sid[grp][j] * DKV + e) & M_DICT];
    acc *= (1.0f / 64.0f);
    sred[grp][e] = acc; __syncthreads();
    #pragma unroll
    for (int s = 32; s > 0; s >>= 1) {
        if (e < s) sred[grp][e] += sred[grp][e + s];
        __syncthreads();
    }
    float mean = sred[grp][0] * (1.0f / 64.0f);
    __syncthreads();
    float diff = acc - mean;
    sred[grp][e] = diff * diff; __syncthreads();
    #pragma unroll
    for (int s = 32; s > 0; s >>= 1) {
        if (e < s) sred[grp][e] += sred[grp][e + s];
        __syncthreads();
    }
    float var = sred[grp][0] * (1.0f / 64.0f);
    float r = diff * rsqrtf(var + 1e-6f) * lng[e & 63] + lnb[e & 63];
    int widx = (bh * 64 + q) * 64 + e;
    if (widx < n_out) out[widx] = r;                   // [b][h][q][e]
}

// ---------------- fallback: zero-fill output ----------------------------------
__global__ void kz_zero(float* __restrict__ out, int n_out) {
    int i = blockIdx.x * 256 + threadIdx.x;
    if (i < n_out) out[i] = 0.0f;
}

// ---------------- launch ------------------------------------------------------
static bool size_ok(int got, int need_elems) {
    return got == need_elems || got == need_elems * 4;   // elements or bytes
}

extern "C" void kernel_launch(void* const* d_in, const int* in_sizes, int n_in,
                              void* d_out, int out_size) {
    int n_out = out_size;
    if (n_out == 65536 * 4 || n_out == 196608 * 4) n_out >>= 2;
    if (n_out < 0) n_out = 0;
    float* out = (float*)d_out;

    const int SZ_BIG = BSX * QL * INNER;       // 65536
    const int SZ_WI  = 2 * INNER * INNER;      // 524288
    const int SZ_DI  = VOC * DKV;              // 262144
    const int SZ_OW  = DKV * DKV;              // 4096
    const int SZ_V   = DKV;                    // 64

    const float *query = 0, *key = 0, *qpe = 0, *kpe = 0, *wi = 0, *dict = 0,
                *ow = 0, *vg = 0, *vb = 0, *lg = 0, *lb = 0;
    bool mapped = false;

    if (n_in >= 11) {
        const int sig[11] = {SZ_BIG, SZ_BIG, SZ_BIG, SZ_BIG, SZ_WI, SZ_DI,
                             SZ_V, SZ_V, SZ_OW, SZ_V, SZ_V};
        bool ok = true;
        for (int i = 0; i < 11; i++) ok = ok && size_ok(in_sizes[i], sig[i]);
        if (ok) {
            query = (const float*)d_in[0];  key = (const float*)d_in[1];
            qpe   = (const float*)d_in[2];  kpe = (const float*)d_in[3];
            wi    = (const float*)d_in[4];  dict = (const float*)d_in[5];
            vg    = (const float*)d_in[6];  vb  = (const float*)d_in[7];
            ow    = (const float*)d_in[8];  lg  = (const float*)d_in[9];
            lb    = (const float*)d_in[10];
            mapped = true;
        }
        if (!mapped) {
            const int alp[11] = {SZ_BIG, SZ_BIG, SZ_V, SZ_V, SZ_BIG, SZ_BIG,
                                 SZ_DI, SZ_V, SZ_V, SZ_OW, SZ_WI};
            bool ok2 = true;
            for (int i = 0; i < 11; i++) ok2 = ok2 && size_ok(in_sizes[i], alp[i]);
            if (ok2) {
                key  = (const float*)d_in[0];  kpe = (const float*)d_in[1];
                lb   = (const float*)d_in[2];  lg  = (const float*)d_in[3];
                qpe  = (const float*)d_in[4];  query = (const float*)d_in[5];
                dict = (const float*)d_in[6];  vb  = (const float*)d_in[7];
                vg   = (const float*)d_in[8];  ow  = (const float*)d_in[9];
                wi   = (const float*)d_in[10];
                mapped = true;
            }
        }
    }

    if (!mapped) {
        if (n_out > 0) kz_zero<<<(n_out + 255) / 256, 256>>>(out, n_out);
        return;
    }

    k0_dict <<<64, 256>>>(dict, vg, vb, ow);
    k1_proj <<<dim3(8, 16, 2), 128>>>(query, key, qpe, kpe, wi);
    kB_main <<<dim3(68, 16), 256>>>();
    kC_final<<<256, 256>>>(lg, lb, out, n_out);
}

// round 15
// speedup vs baseline: 1.0525x; 1.0002x over previous
#include <cuda_runtime.h>
#include <math.h>

// Problem constants
#define BSX   2
#define QL    64
#define KLN   64
#define NH    8
#define DKV   64
#define INNER 512
#define VOC   4096
#define NBH   16          // BSX * NH
#define VSPL  64          // v-range splits (64 v each)

// Masks (all scratch arrays are power-of-2 element counts)
#define M_PROJ 0xFFFFu     // 65536
#define M_DICT 0x3FFFFu    // 262144
#define M_AB   0x3FFFFFu   // 4194304
#define M_NRM  0x3FFu      // 1024
#define M_G    0xFFFFu     // 65536
#define M_P    0x3FFFFFu   // 4194304

typedef unsigned long long u64;
#define ADD_F32X2(out, a, b) \
    asm("add.rn.f32x2 %0, %1, %2;" : "=l"(out) : "l"(a), "l"(b))

// ---------------- scratch (device globals; no allocation allowed) -------------
__device__ float g_qproj[BSX * QL * INNER];        // 65536
__device__ float g_kproj[BSX * KLN * INNER];       // 65536
__device__ float g_dnT[DKV * VOC];                 // l2 dict [d][v]  262144
__device__ float g_dp[VOC * DKV];                  // LN(dict)@O      262144
__device__ float g_A[NBH * QL * VOC];              // 4194304
__device__ float g_Bm[NBH * KLN * VOC];            // 4194304
__device__ float g_nq[NBH * QL];                   // 1024
__device__ float g_nk[NBH * KLN];                  // 1024
__device__ float g_G[NBH * QL * KLN];              // 65536
__device__ float g_pv[NBH * QL * KLN * VSPL];      // 4194304

// ---------------- K0: dict preprocessing (l2norm(T) + LN@O) -------------------
__global__ void k0_dict(const float* __restrict__ dict,
                        const float* __restrict__ vg,
                        const float* __restrict__ vb,
                        const float* __restrict__ O) {
    __shared__ float sn[64][65];                       // [d][vlocal]
    int l = threadIdx.x & 31, warp = threadIdx.x >> 5;
    int v0 = blockIdx.x * 64;
    #pragma unroll
    for (int i = 0; i < 8; i++) {
        int vl = warp * 8 + i;
        int r = v0 + vl;
        float x0 = dict[(r * DKV + l) & M_DICT];
        float x1 = dict[(r * DKV + 32 + l) & M_DICT];

        float s = x0 * x0 + x1 * x1;
        #pragma unroll
        for (int o = 16; o > 0; o >>= 1) s += __shfl_xor_sync(0xffffffffu, s, o);
        float inv = rsqrtf(fmaxf(s, 1e-12f));
        sn[l][vl]      = x0 * inv;
        sn[l + 32][vl] = x1 * inv;

        float m = x0 + x1;
        #pragma unroll
        for (int o = 16; o > 0; o >>= 1) m += __shfl_xor_sync(0xffffffffu, m, o);
        m *= (1.0f / 64.0f);
        float d0 = x0 - m, d1 = x1 - m;
        float v = d0 * d0 + d1 * d1;
        #pragma unroll
        for (int o = 16; o > 0; o >>= 1) v += __shfl_xor_sync(0xffffffffu, v, o);
        v *= (1.0f / 64.0f);
        float rs = rsqrtf(v + 1e-6f);
        float ln0 = d0 * rs * vg[l & 63]        + vb[l & 63];
        float ln1 = d1 * rs * vg[(l + 32) & 63] + vb[(l + 32) & 63];

        float a0 = 0.f, a1 = 0.f;
        #pragma unroll
        for (int d2 = 0; d2 < 32; d2++) {
            float t = __shfl_sync(0xffffffffu, ln0, d2);
            a0 += t * O[(d2 * 64 + l) & 4095];
            a1 += t * O[(d2 * 64 + 32 + l) & 4095];
        }
        #pragma unroll
        for (int d2 = 0; d2 < 32; d2++) {
            float t = __shfl_sync(0xffffffffu, ln1, d2);
            a0 += t * O[((32 + d2) * 64 + l) & 4095];
            a1 += t * O[((32 + d2) * 64 + 32 + l) & 4095];
        }
        g_dp[(r * DKV + l) & M_DICT]      = a0;
        g_dp[(r * DKV + 32 + l) & M_DICT] = a1;
    }
    __syncthreads();
    for (int i = threadIdx.x; i < 64 * 64; i += 256) {
        int d = i >> 6, vl = i & 63;
        g_dnT[(d * VOC + v0 + vl) & M_DICT] = sn[d][vl];
    }
}

// ---------------- K1: q_proj / k_proj GEMM ------------------------------------
__global__ void k1_proj(const float* __restrict__ q, const float* __restrict__ k,
                        const float* __restrict__ qpe, const float* __restrict__ kpe,
                        const float* __restrict__ wi) {
    __shared__ __align__(16) float xs[8][INNER];
    int side = blockIdx.z;
    const float* xin = side ? k   : q;
    const float* pin = side ? kpe : qpe;
    const float* W   = wi + side * (INNER * INNER);
    float* out = side ? g_kproj : g_qproj;
    int m0 = blockIdx.y * 8;
    int tid = threadIdx.x;                             // 128 threads
    for (int i = tid; i < 8 * INNER; i += 128) {
        int r = i >> 9, d = i & 511;
        int gidx = ((m0 + r) * INNER + d) & M_PROJ;
        xs[r][d] = xin[gidx] + pin[gidx];
    }
    __syncthreads();
    int e  = blockIdx.x * 64 + (tid & 63);             // 0..511
    int r0 = (tid >> 6) * 4;                           // 0 or 4
    float acc[4] = {};
    for (int d = 0; d < INNER; d += 4) {
        float w0 = W[((d + 0) * INNER + e) & 0x3FFFF];
        float w1 = W[((d + 1) * INNER + e) & 0x3FFFF];
        float w2 = W[((d + 2) * INNER + e) & 0x3FFFF];
        float w3 = W[((d + 3) * INNER + e) & 0x3FFFF];
        #pragma unroll
        for (int r = 0; r < 4; r++) {
            float4 xv = *(const float4*)&xs[r0 + r][d];
            acc[r] += xv.x * w0 + xv.y * w1 + xv.z * w2 + xv.w * w3;
        }
    }
    #pragma unroll
    for (int r = 0; r < 4; r++)
        out[((m0 + r0 + r) * INNER + e) & M_PROJ] = acc[r];
}

// ---------------- kB: fused GEMM+max (x<64) and per-head Gram (x=64..67) ------
__global__ void __launch_bounds__(256, 4) kB_main() {
    __shared__ union SU {
        struct { float xsT[32][132]; float dst[32][68]; } p1;  // GEMM inputs
        float Ps[128][68];                                     // GEMM outputs
        struct { float qs[16][65]; float ks[64][65]; } g1;     // gram
    } su;
    int bh = blockIdx.y;                               // 0..15
    int b = bh >> 3, h = bh & 7;
    int tid = threadIdx.x;                             // 256

    if (blockIdx.x >= 64) {
        // ---- per-head Gram matrix + row norms ----
        int qt = blockIdx.x - 64;                      // 0..3
        for (int i = tid; i < 16 * 64; i += 256) {
            int r = i >> 6, d = i & 63;
            su.g1.qs[r][d] = g_qproj[((b * 64 + qt * 16 + r) * INNER + h * 64 + d) & M_PROJ];
        }
        for (int i = tid; i < 64 * 64; i += 256) {
            int r = i >> 6, d = i & 63;
            su.g1.ks[r][d] = g_kproj[((b * 64 + r) * INNER + h * 64 + d) & M_PROJ];
        }
        __syncthreads();
        int qq = tid >> 4;                             // 0..15
        int kb = (tid & 15) * 4;                       // 4 k each
        float acc[4] = {};
        for (int d = 0; d < 64; d++) {
            float a = su.g1.qs[qq][d];
            #pragma unroll
            for (int j = 0; j < 4; j++) acc[j] += a * su.g1.ks[kb + j][d];
        }
        #pragma unroll
        for (int j = 0; j < 4; j++)
            g_G[((bh * 64 + qt * 16 + qq) * 64 + kb + j) & M_G] = acc[j];
        if (tid < 16) {
            float s = 0.f;
            #pragma unroll 8
            for (int d = 0; d < 64; d++) { float x = su.g1.qs[tid][d]; s += x * x; }
            g_nq[(bh * 64 + qt * 16 + tid) & M_NRM] = s;
        } else if (qt == 0 && tid >= 64 && tid < 128) {
            int r = tid - 64;
            float s = 0.f;
            #pragma unroll 8
            for (int d = 0; d < 64; d++) { float x = su.g1.ks[r][d]; s += x * x; }
            g_nk[(bh * 64 + r) & M_NRM] = s;
        }
        return;
    }

    // ---- fused GEMM (scalar FFMA) + conflict-free max ----
    int vc = blockIdx.x;                               // 0..63
    int v0 = vc * 64;
    int tv = tid & 7, tr = tid >> 3;                   // 8 v-groups x 32 row-groups
    float acc[4][8] = {};

    #pragma unroll
    for (int c = 0; c < 2; c++) {
        __syncthreads();
        for (int i = tid; i < 128 * 8; i += 256) {
            int r = i >> 3, d4 = (i & 7) * 4;
            const float* src = (r < 64) ? g_qproj : g_kproj;
            int g = ((b * 64 + (r & 63)) * INNER + h * 64 + c * 32 + d4) & (M_PROJ & ~3u);
            float4 vv = *(const float4*)&src[g];
            su.p1.xsT[d4 + 0][r] = vv.x; su.p1.xsT[d4 + 1][r] = vv.y;
            su.p1.xsT[d4 + 2][r] = vv.z; su.p1.xsT[d4 + 3][r] = vv.w;
        }
        for (int i = tid; i < 32 * 16; i += 256) {
            int d = i >> 4, m4 = (i & 15) * 4;
            int g = ((c * 32 + d) * VOC + v0 + m4) & (M_DICT & ~3u);
            *(float4*)&su.p1.dst[d][m4] = *(const float4*)&g_dnT[g];
        }
        __syncthreads();
        #pragma unroll 8
        for (int d = 0; d < 32; d++) {
            float4 xv  = *(const float4*)&su.p1.xsT[d][tr * 4];
            float4 dv0 = *(const float4*)&su.p1.dst[d][tv * 8];
            float4 dv1 = *(const float4*)&su.p1.dst[d][tv * 8 + 4];
            float xa[4] = {xv.x, xv.y, xv.z, xv.w};
            #pragma unroll
            for (int i = 0; i < 4; i++) {
                float a = xa[i];
                acc[i][0] += a * dv0.x; acc[i][1] += a * dv0.y;
                acc[i][2] += a * dv0.z; acc[i][3] += a * dv0.w;
                acc[i][4] += a * dv1.x; acc[i][5] += a * dv1.y;
                acc[i][6] += a * dv1.z; acc[i][7] += a * dv1.w;
            }
        }
    }
    __syncthreads();                                   // done with p1; reuse as Ps
    #pragma unroll
    for (int i = 0; i < 4; i++) {
        int r = tr * 4 + i;                            // 0..127
        float4 s0 = make_float4(acc[i][0], acc[i][1], acc[i][2], acc[i][3]);
        float4 s1 = make_float4(acc[i][4], acc[i][5], acc[i][6], acc[i][7]);
        *(float4*)&su.Ps[r][tv * 8]     = s0;
        *(float4*)&su.Ps[r][tv * 8 + 4] = s1;
        float* out = (r < 64) ? g_A : g_Bm;
        int base = ((bh * 64 + (r & 63)) * VOC + v0 + tv * 8) & (M_AB & ~3u);
        *(float4*)&out[base]     = s0;
        *(float4*)&out[base + 4] = s1;
    }
    __syncthreads();

    // max phase: conflict-free. thread = (tq8 = tid&7, tk32 = tid>>3):
    //   q rows = tq8 + 8i (i<8); k rows = tk32 + 32j (j<2)
    int tq8 = tid & 7, tk32 = tid >> 3;
    float best[8][2];
    #pragma unroll
    for (int i = 0; i < 8; i++) { best[i][0] = -3.402823466e38f; best[i][1] = -3.402823466e38f; }
    #pragma unroll
    for (int v = 0; v < 64; v += 4) {
        ulonglong2 b0 = *(const ulonglong2*)&su.Ps[64 + tk32][v];
        ulonglong2 b1 = *(const ulonglong2*)&su.Ps[96 + tk32][v];
        #pragma unroll
        for (int i = 0; i < 8; i++) {
            ulonglong2 aa = *(const ulonglong2*)&su.Ps[tq8 + 8 * i][v];
            u64 c0, c1;
            ADD_F32X2(c0, aa.x, b0.x);
            ADD_F32X2(c1, aa.y, b0.y);
            {
                float2 f0 = *reinterpret_cast<float2*>(&c0);
                float2 f1 = *reinterpret_cast<float2*>(&c1);
                best[i][0] = fmaxf(best[i][0],
                                   fmaxf(fmaxf(f0.x, f0.y), fmaxf(f1.x, f1.y)));
            }
            ADD_F32X2(c0, aa.x, b1.x);
            ADD_F32X2(c1, aa.y, b1.y);
            {
                float2 f0 = *reinterpret_cast<float2*>(&c0);
                float2 f1 = *reinterpret_cast<float2*>(&c1);
                best[i][1] = fmaxf(best[i][1],
                                   fmaxf(fmaxf(f0.x, f0.y), fmaxf(f1.x, f1.y)));
            }
        }
    }
    #pragma unroll
    for (int i = 0; i < 8; i++)
        #pragma unroll
        for (int j = 0; j < 2; j++) {
            int qr = tq8 + 8 * i, kk = tk32 + 32 * j;
            int pair = (bh * 64 + qr) * 64 + kk;
            g_pv[(pair * VSPL + vc) & M_P] = best[i][j];
        }
}

// ---------------- kC: merge + index recovery + ws + weighted sum + LN ---------
// 512 blocks x 128 threads; block covers 128 pairs = one bh, 2 q-values, 64 kk.
__global__ void kC_final(const float* __restrict__ lng, const float* __restrict__ lnb,
                         float* __restrict__ out, int n_out) {
    __shared__ float sws[2][64];
    __shared__ int   sid[2][64];
    __shared__ float sred[2][64];
    int tid = threadIdx.x;                             // 128
    int p = blockIdx.x * 128 + tid;                    // 0..65535
    int bh = p >> 12, q = (p >> 6) & 63, kk = p & 63;

    float bv = -3.402823466e38f; int sp = 0;
    #pragma unroll
    for (int j = 0; j < VSPL; j += 4) {
        float4 v4 = *(const float4*)&g_pv[((p * VSPL) + j) & (M_P & ~3u)];
        if (v4.x > bv) { bv = v4.x; sp = j; }
        if (v4.y > bv) { bv = v4.y; sp = j + 1; }
        if (v4.z > bv) { bv = v4.z; sp = j + 2; }
        if (v4.w > bv) { bv = v4.w; sp = j + 3; }
    }
    int rowA = (bh * 64 + q)  * VOC + sp * 64;
    int rowB = (bh * 64 + kk) * VOC + sp * 64;
    int bi = -1;
    #pragma unroll 4
    for (int v = 0; v < 64; v += 4) {
        float4 a4 = *(const float4*)&g_A [(rowA + v) & (M_AB & ~3u)];
        float4 b4 = *(const float4*)&g_Bm[(rowB + v) & (M_AB & ~3u)];
        if (bi < 0) {
            if      (a4.x + b4.x == bv) bi = sp * 64 + v;
            else if (a4.y + b4.y == bv) bi = sp * 64 + v + 1;
            else if (a4.z + b4.z == bv) bi = sp * 64 + v + 2;
            else if (a4.w + b4.w == bv) bi = sp * 64 + v + 3;
        }
    }
    if (bi < 0) bi = 0;                                // unreachable; safety

    float n2 = g_nq[(bh * 64 + q) & M_NRM] + g_nk[(bh * 64 + kk) & M_NRM]
             + 2.0f * g_G[((bh * 64 + q) * 64 + kk) & M_G];
    float ws = bv * rsqrtf(fmaxf(n2, 1e-12f));

    int b = bh >> 3, h = bh & 7;
    int oidx = ((b * 64 + q) * 64 + kk) * 8 + h;
    if (65536 + oidx < n_out)  out[65536  + oidx] = (float)bi;  // out_ids
    if (131072 + oidx < n_out) out[131072 + oidx] = ws;         // r3_scores

    int grp = tid >> 6;                                // 0 or 1 (= q parity slot)
    sws[grp][kk] = ws;
    sid[grp][kk] = bi;
    __syncthreads();

    // weighted sum + layernorm: group grp handles (bh, q); e = tid&63
    int e = tid & 63;
    float acc = 0.f;
    #pragma unroll 4
    for (int j = 0; j < 64; j++)
        acc += sws[grp][j] * g_dp[(sid[grp][j] * DKV + e) & M_DICT];
    acc *= (1.0f / 64.0f);
    sred[grp][e] = acc; __syncthreads();
    #pragma unroll
    for (int s = 32; s > 0; s >>= 1) {
        if (e < s) sred[grp][e] += sred[grp][e + s];
        __syncthreads();
    }
    float mean = sred[grp][0] * (1.0f / 64.0f);
    __syncthreads();
    float diff = acc - mean;
    sred[grp][e] = diff * diff; __syncthreads();
    #pragma unroll
    for (int s = 32; s > 0; s >>= 1) {
        if (e < s) sred[grp][e] += sred[grp][e + s];
        __syncthreads();
    }
    float var = sred[grp][0] * (1.0f / 64.0f);
    float r = diff * rsqrtf(var + 1e-6f) * lng[e & 63] + lnb[e & 63];
    int widx = (bh * 64 + q) * 64 + e;
    if (widx < n_out) out[widx] = r;                   // [b][h][q][e]
}

// ---------------- fallback: zero-fill output ----------------------------------
__global__ void kz_zero(float* __restrict__ out, int n_out) {
    int i = blockIdx.x * 256 + threadIdx.x;
    if (i < n_out) out[i] = 0.0f;
}

// ---------------- launch ------------------------------------------------------
static bool size_ok(int got, int need_elems) {
    return got == need_elems || got == need_elems * 4;   // elements or bytes
}

extern "C" void kernel_launch(void* const* d_in, const int* in_sizes, int n_in,
                              void* d_out, int out_size) {
    int n_out = out_size;
    if (n_out == 65536 * 4 || n_out == 196608 * 4) n_out >>= 2;
    if (n_out < 0) n_out = 0;
    float* out = (float*)d_out;

    const int SZ_BIG = BSX * QL * INNER;       // 65536
    const int SZ_WI  = 2 * INNER * INNER;      // 524288
    const int SZ_DI  = VOC * DKV;              // 262144
    const int SZ_OW  = DKV * DKV;              // 4096
    const int SZ_V   = DKV;                    // 64

    const float *query = 0, *key = 0, *qpe = 0, *kpe = 0, *wi = 0, *dict = 0,
                *ow = 0, *vg = 0, *vb = 0, *lg = 0, *lb = 0;
    bool mapped = false;

    if (n_in >= 11) {
        const int sig[11] = {SZ_BIG, SZ_BIG, SZ_BIG, SZ_BIG, SZ_WI, SZ_DI,
                             SZ_V, SZ_V, SZ_OW, SZ_V, SZ_V};
        bool ok = true;
        for (int i = 0; i < 11; i++) ok = ok && size_ok(in_sizes[i], sig[i]);
        if (ok) {
            query = (const float*)d_in[0];  key = (const float*)d_in[1];
            qpe   = (const float*)d_in[2];  kpe = (const float*)d_in[3];
            wi    = (const float*)d_in[4];  dict = (const float*)d_in[5];
            vg    = (const float*)d_in[6];  vb  = (const float*)d_in[7];
            ow    = (const float*)d_in[8];  lg  = (const float*)d_in[9];
            lb    = (const float*)d_in[10];
            mapped = true;
        }
        if (!mapped) {
            const int alp[11] = {SZ_BIG, SZ_BIG, SZ_V, SZ_V, SZ_BIG, SZ_BIG,
                                 SZ_DI, SZ_V, SZ_V, SZ_OW, SZ_WI};
            bool ok2 = true;
            for (int i = 0; i < 11; i++) ok2 = ok2 && size_ok(in_sizes[i], alp[i]);
            if (ok2) {
                key  = (const float*)d_in[0];  kpe = (const float*)d_in[1];
                lb   = (const float*)d_in[2];  lg  = (const float*)d_in[3];
                qpe  = (const float*)d_in[4];  query = (const float*)d_in[5];
                dict = (const float*)d_in[6];  vb  = (const float*)d_in[7];
                vg   = (const float*)d_in[8];  ow  = (const float*)d_in[9];
                wi   = (const float*)d_in[10];
                mapped = true;
            }
        }
    }

    if (!mapped) {
        if (n_out > 0) kz_zero<<<(n_out + 255) / 256, 256>>>(out, n_out);
        return;
    }

    k0_dict <<<64, 256>>>(dict, vg, vb, ow);
    k1_proj <<<dim3(8, 16, 2), 128>>>(query, key, qpe, kpe, wi);
    kB_main <<<dim3(68, 16), 256>>>();
    kC_final<<<512, 128>>>(lg, lb, out, n_out);
}

// round 16
// speedup vs baseline: 1.2241x; 1.1630x over previous
#include <cuda_runtime.h>
#include <math.h>

// Problem constants
#define BSX   2
#define QL    64
#define KLN   64
#define NH    8
#define DKV   64
#define INNER 512
#define VOC   4096
#define NBH   16          // BSX * NH
#define VSPL  64          // v-range splits (64 v each)

// Masks (all scratch arrays are power-of-2 element counts)
#define M_PROJ 0xFFFFu     // 65536
#define M_DICT 0x3FFFFu    // 262144
#define M_AB   0x3FFFFFu   // 4194304
#define M_NRM  0x3FFu      // 1024
#define M_G    0xFFFFu     // 65536
#define M_W    0xFFFFu     // 65536

typedef unsigned long long u64;
#define ADD_F32X2(out, a, b) \
    asm("add.rn.f32x2 %0, %1, %2;" : "=l"(out) : "l"(a), "l"(b))

// ---------------- scratch (device globals; no allocation allowed) -------------
__device__ float g_qproj[BSX * QL * INNER];        // 65536
__device__ float g_kproj[BSX * KLN * INNER];       // 65536
__device__ float g_dnT[DKV * VOC];                 // l2 dict [d][v]  262144
__device__ float g_dp[VOC * DKV];                  // LN(dict)@O      262144
__device__ float g_A[NBH * QL * VOC];              // 4194304
__device__ float g_Bm[NBH * KLN * VOC];            // 4194304
__device__ float g_nq[NBH * QL];                   // 1024
__device__ float g_nk[NBH * KLN];                  // 1024
__device__ float g_G[NBH * QL * KLN];              // 65536
__device__ u64   g_amax[NBH * QL * KLN];           // packed (key|63-vc) 65536

// ---------------- K0: reset g_amax + dict preprocessing -----------------------
__global__ void k0_dict(const float* __restrict__ dict,
                        const float* __restrict__ vg,
                        const float* __restrict__ vb,
                        const float* __restrict__ O) {
    __shared__ float sn[64][65];                       // [d][vlocal]
    // reset the atomic-max table (64 blocks x 256 threads x 4 = 65536)
    {
        int gt = blockIdx.x * 256 + threadIdx.x;
        #pragma unroll
        for (int z = 0; z < 4; z++) g_amax[(gt * 4 + z) & M_W] = 0ull;
    }
    int l = threadIdx.x & 31, warp = threadIdx.x >> 5;
    int v0 = blockIdx.x * 64;
    #pragma unroll
    for (int i = 0; i < 8; i++) {
        int vl = warp * 8 + i;
        int r = v0 + vl;
        float x0 = dict[(r * DKV + l) & M_DICT];
        float x1 = dict[(r * DKV + 32 + l) & M_DICT];

        float s = x0 * x0 + x1 * x1;
        #pragma unroll
        for (int o = 16; o > 0; o >>= 1) s += __shfl_xor_sync(0xffffffffu, s, o);
        float inv = rsqrtf(fmaxf(s, 1e-12f));
        sn[l][vl]      = x0 * inv;
        sn[l + 32][vl] = x1 * inv;

        float m = x0 + x1;
        #pragma unroll
        for (int o = 16; o > 0; o >>= 1) m += __shfl_xor_sync(0xffffffffu, m, o);
        m *= (1.0f / 64.0f);
        float d0 = x0 - m, d1 = x1 - m;
        float v = d0 * d0 + d1 * d1;
        #pragma unroll
        for (int o = 16; o > 0; o >>= 1) v += __shfl_xor_sync(0xffffffffu, v, o);
        v *= (1.0f / 64.0f);
        float rs = rsqrtf(v + 1e-6f);
        float ln0 = d0 * rs * vg[l & 63]        + vb[l & 63];
        float ln1 = d1 * rs * vg[(l + 32) & 63] + vb[(l + 32) & 63];

        float a0 = 0.f, a1 = 0.f;
        #pragma unroll
        for (int d2 = 0; d2 < 32; d2++) {
            float t = __shfl_sync(0xffffffffu, ln0, d2);
            a0 += t * O[(d2 * 64 + l) & 4095];
            a1 += t * O[(d2 * 64 + 32 + l) & 4095];
        }
        #pragma unroll
        for (int d2 = 0; d2 < 32; d2++) {
            float t = __shfl_sync(0xffffffffu, ln1, d2);
            a0 += t * O[((32 + d2) * 64 + l) & 4095];
            a1 += t * O[((32 + d2) * 64 + 32 + l) & 4095];
        }
        g_dp[(r * DKV + l) & M_DICT]      = a0;
        g_dp[(r * DKV + 32 + l) & M_DICT] = a1;
    }
    __syncthreads();
    for (int i = threadIdx.x; i < 64 * 64; i += 256) {
        int d = i >> 6, vl = i & 63;
        g_dnT[(d * VOC + v0 + vl) & M_DICT] = sn[d][vl];
    }
}

// ---------------- K1: q_proj / k_proj GEMM ------------------------------------
__global__ void k1_proj(const float* __restrict__ q, const float* __restrict__ k,
                        const float* __restrict__ qpe, const float* __restrict__ kpe,
                        const float* __restrict__ wi) {
    __shared__ __align__(16) float xs[8][INNER];
    int side = blockIdx.z;
    const float* xin = side ? k   : q;
    const float* pin = side ? kpe : qpe;
    const float* W   = wi + side * (INNER * INNER);
    float* out = side ? g_kproj : g_qproj;
    int m0 = blockIdx.y * 8;
    int tid = threadIdx.x;                             // 128 threads
    for (int i = tid; i < 8 * INNER; i += 128) {
        int r = i >> 9, d = i & 511;
        int gidx = ((m0 + r) * INNER + d) & M_PROJ;
        xs[r][d] = xin[gidx] + pin[gidx];
    }
    __syncthreads();
    int e  = blockIdx.x * 64 + (tid & 63);             // 0..511
    int r0 = (tid >> 6) * 4;                           // 0 or 4
    float acc[4] = {};
    for (int d = 0; d < INNER; d += 4) {
        float w0 = W[((d + 0) * INNER + e) & 0x3FFFF];
        float w1 = W[((d + 1) * INNER + e) & 0x3FFFF];
        float w2 = W[((d + 2) * INNER + e) & 0x3FFFF];
        float w3 = W[((d + 3) * INNER + e) & 0x3FFFF];
        #pragma unroll
        for (int r = 0; r < 4; r++) {
            float4 xv = *(const float4*)&xs[r0 + r][d];
            acc[r] += xv.x * w0 + xv.y * w1 + xv.z * w2 + xv.w * w3;
        }
    }
    #pragma unroll
    for (int r = 0; r < 4; r++)
        out[((m0 + r0 + r) * INNER + e) & M_PROJ] = acc[r];
}

// ---------------- kB: fused GEMM+max (x<64) and per-head Gram (x=64..67) ------
__global__ void __launch_bounds__(256, 4) kB_main() {
    __shared__ union SU {
        struct { float xsT[32][132]; float dst[32][68]; } p1;  // GEMM inputs
        float Ps[128][68];                                     // GEMM outputs
        struct { float qs[16][65]; float ks[64][65]; } g1;     // gram
    } su;
    int bh = blockIdx.y;                               // 0..15
    int b = bh >> 3, h = bh & 7;
    int tid = threadIdx.x;                             // 256

    if (blockIdx.x >= 64) {
        // ---- per-head Gram matrix + row norms ----
        int qt = blockIdx.x - 64;                      // 0..3
        for (int i = tid; i < 16 * 64; i += 256) {
            int r = i >> 6, d = i & 63;
            su.g1.qs[r][d] = g_qproj[((b * 64 + qt * 16 + r) * INNER + h * 64 + d) & M_PROJ];
        }
        for (int i = tid; i < 64 * 64; i += 256) {
            int r = i >> 6, d = i & 63;
            su.g1.ks[r][d] = g_kproj[((b * 64 + r) * INNER + h * 64 + d) & M_PROJ];
        }
        __syncthreads();
        int qq = tid >> 4;                             // 0..15
        int kb = (tid & 15) * 4;                       // 4 k each
        float acc[4] = {};
        for (int d = 0; d < 64; d++) {
            float a = su.g1.qs[qq][d];
            #pragma unroll
            for (int j = 0; j < 4; j++) acc[j] += a * su.g1.ks[kb + j][d];
        }
        #pragma unroll
        for (int j = 0; j < 4; j++)
            g_G[((bh * 64 + qt * 16 + qq) * 64 + kb + j) & M_G] = acc[j];
        if (tid < 16) {
            float s = 0.f;
            #pragma unroll 8
            for (int d = 0; d < 64; d++) { float x = su.g1.qs[tid][d]; s += x * x; }
            g_nq[(bh * 64 + qt * 16 + tid) & M_NRM] = s;
        } else if (qt == 0 && tid >= 64 && tid < 128) {
            int r = tid - 64;
            float s = 0.f;
            #pragma unroll 8
            for (int d = 0; d < 64; d++) { float x = su.g1.ks[r][d]; s += x * x; }
            g_nk[(bh * 64 + r) & M_NRM] = s;
        }
        return;
    }

    // ---- fused GEMM (scalar FFMA) + conflict-free max ----
    int vc = blockIdx.x;                               // 0..63
    int v0 = vc * 64;
    int tv = tid & 7, tr = tid >> 3;                   // 8 v-groups x 32 row-groups
    float acc[4][8] = {};

    #pragma unroll
    for (int c = 0; c < 2; c++) {
        __syncthreads();
        for (int i = tid; i < 128 * 8; i += 256) {
            int r = i >> 3, d4 = (i & 7) * 4;
            const float* src = (r < 64) ? g_qproj : g_kproj;
            int g = ((b * 64 + (r & 63)) * INNER + h * 64 + c * 32 + d4) & (M_PROJ & ~3u);
            float4 vv = *(const float4*)&src[g];
            su.p1.xsT[d4 + 0][r] = vv.x; su.p1.xsT[d4 + 1][r] = vv.y;
            su.p1.xsT[d4 + 2][r] = vv.z; su.p1.xsT[d4 + 3][r] = vv.w;
        }
        for (int i = tid; i < 32 * 16; i += 256) {
            int d = i >> 4, m4 = (i & 15) * 4;
            int g = ((c * 32 + d) * VOC + v0 + m4) & (M_DICT & ~3u);
            *(float4*)&su.p1.dst[d][m4] = *(const float4*)&g_dnT[g];
        }
        __syncthreads();
        #pragma unroll 8
        for (int d = 0; d < 32; d++) {
            float4 xv  = *(const float4*)&su.p1.xsT[d][tr * 4];
            float4 dv0 = *(const float4*)&su.p1.dst[d][tv * 8];
            float4 dv1 = *(const float4*)&su.p1.dst[d][tv * 8 + 4];
            float xa[4] = {xv.x, xv.y, xv.z, xv.w};
            #pragma unroll
            for (int i = 0; i < 4; i++) {
                float a = xa[i];
                acc[i][0] += a * dv0.x; acc[i][1] += a * dv0.y;
                acc[i][2] += a * dv0.z; acc[i][3] += a * dv0.w;
                acc[i][4] += a * dv1.x; acc[i][5] += a * dv1.y;
                acc[i][6] += a * dv1.z; acc[i][7] += a * dv1.w;
            }
        }
    }
    __syncthreads();                                   // done with p1; reuse as Ps
    #pragma unroll
    for (int i = 0; i < 4; i++) {
        int r = tr * 4 + i;                            // 0..127
        float4 s0 = make_float4(acc[i][0], acc[i][1], acc[i][2], acc[i][3]);
        float4 s1 = make_float4(acc[i][4], acc[i][5], acc[i][6], acc[i][7]);
        *(float4*)&su.Ps[r][tv * 8]     = s0;
        *(float4*)&su.Ps[r][tv * 8 + 4] = s1;
        float* out = (r < 64) ? g_A : g_Bm;
        int base = ((bh * 64 + (r & 63)) * VOC + v0 + tv * 8) & (M_AB & ~3u);
        *(float4*)&out[base]     = s0;
        *(float4*)&out[base + 4] = s1;
    }
    __syncthreads();

    // max phase: conflict-free. thread = (tq8 = tid&7, tk32 = tid>>3):
    //   q rows = tq8 + 8i (i<8); k rows = tk32 + 32j (j<2)
    int tq8 = tid & 7, tk32 = tid >> 3;
    float best[8][2];
    #pragma unroll
    for (int i = 0; i < 8; i++) { best[i][0] = -3.402823466e38f; best[i][1] = -3.402823466e38f; }
    #pragma unroll
    for (int v = 0; v < 64; v += 4) {
        ulonglong2 b0 = *(const ulonglong2*)&su.Ps[64 + tk32][v];
        ulonglong2 b1 = *(const ulonglong2*)&su.Ps[96 + tk32][v];
        #pragma unroll
        for (int i = 0; i < 8; i++) {
            ulonglong2 aa = *(const ulonglong2*)&su.Ps[tq8 + 8 * i][v];
            u64 c0, c1;
            ADD_F32X2(c0, aa.x, b0.x);
            ADD_F32X2(c1, aa.y, b0.y);
            {
                float2 f0 = *reinterpret_cast<float2*>(&c0);
                float2 f1 = *reinterpret_cast<float2*>(&c1);
                best[i][0] = fmaxf(best[i][0],
                                   fmaxf(fmaxf(f0.x, f0.y), fmaxf(f1.x, f1.y)));
            }
            ADD_F32X2(c0, aa.x, b1.x);
            ADD_F32X2(c1, aa.y, b1.y);
            {
                float2 f0 = *reinterpret_cast<float2*>(&c0);
                float2 f1 = *reinterpret_cast<float2*>(&c1);
                best[i][1] = fmaxf(best[i][1],
                                   fmaxf(fmaxf(f0.x, f0.y), fmaxf(f1.x, f1.y)));
            }
        }
    }
    // packed atomic max: key = orderable(best) in high 32, (63-vc) in low bits
    // -> larger value wins; on equal value, SMALLER vc wins (first-max ties).
    #pragma unroll
    for (int i = 0; i < 8; i++)
        #pragma unroll
        for (int j = 0; j < 2; j++) {
            int qr = tq8 + 8 * i, kk = tk32 + 32 * j;
            int pair = (bh * 64 + qr) * 64 + kk;
            unsigned int ub = __float_as_uint(best[i][j]);
            ub = ((int)ub < 0) ? ~ub : (ub | 0x80000000u);
            u64 packed = ((u64)ub << 32) | (u64)(63 - vc);
            atomicMax(&g_amax[pair & M_W], packed);
        }
}

// ---------------- kC: unpack + index recovery + ws + weighted sum + LN --------
// 512 blocks x 128 threads; block covers 128 pairs = one bh, 2 q-values, 64 kk.
__global__ void kC_final(const float* __restrict__ lng, const float* __restrict__ lnb,
                         float* __restrict__ out, int n_out) {
    __shared__ float sws[2][64];
    __shared__ int   sid[2][64];
    __shared__ float sred[2][64];
    int tid = threadIdx.x;                             // 128
    int p = blockIdx.x * 128 + tid;                    // 0..65535
    int bh = p >> 12, q = (p >> 6) & 63, kk = p & 63;

    // unpack winner (value + chunk) from the atomic-max table
    u64 packed = g_amax[p & M_W];
    int sp = 63 - (int)(packed & 63u);
    unsigned int kx = (unsigned int)(packed >> 32);
    unsigned int ub = (kx & 0x80000000u) ? (kx ^ 0x80000000u) : ~kx;
    float bv = __uint_as_float(ub);

    int rowA = (bh * 64 + q)  * VOC + sp * 64;
    int rowB = (bh * 64 + kk) * VOC + sp * 64;
    int bi = -1;
    #pragma unroll 4
    for (int v = 0; v < 64; v += 4) {
        float4 a4 = *(const float4*)&g_A [(rowA + v) & (M_AB & ~3u)];
        float4 b4 = *(const float4*)&g_Bm[(rowB + v) & (M_AB & ~3u)];
        if (bi < 0) {
            if      (a4.x + b4.x == bv) bi = sp * 64 + v;
            else if (a4.y + b4.y == bv) bi = sp * 64 + v + 1;
            else if (a4.z + b4.z == bv) bi = sp * 64 + v + 2;
            else if (a4.w + b4.w == bv) bi = sp * 64 + v + 3;
        }
    }
    if (bi < 0) bi = 0;                                // unreachable; safety

    float n2 = g_nq[(bh * 64 + q) & M_NRM] + g_nk[(bh * 64 + kk) & M_NRM]
             + 2.0f * g_G[((bh * 64 + q) * 64 + kk) & M_G];
    float ws = bv * rsqrtf(fmaxf(n2, 1e-12f));

    int b = bh >> 3, h = bh & 7;
    int oidx = ((b * 64 + q) * 64 + kk) * 8 + h;
    if (65536 + oidx < n_out)  out[65536  + oidx] = (float)bi;  // out_ids
    if (131072 + oidx < n_out) out[131072 + oidx] = ws;         // r3_scores

    int grp = tid >> 6;                                // 0 or 1
    sws[grp][kk] = ws;
    sid[grp][kk] = bi;
    __syncthreads();

    // weighted sum + layernorm: group grp handles (bh, q); e = tid&63
    int e = tid & 63;
    float acc = 0.f;
    #pragma unroll 4
    for (int j = 0; j < 64; j++)
        acc += sws[grp][j] * g_dp[(sid[grp][j] * DKV + e) & M_DICT];
    acc *= (1.0f / 64.0f);
    sred[grp][e] = acc; __syncthreads();
    #pragma unroll
    for (int s = 32; s > 0; s >>= 1) {
        if (e < s) sred[grp][e] += sred[grp][e + s];
        __syncthreads();
    }
    float mean = sred[grp][0] * (1.0f / 64.0f);
    __syncthreads();
    float diff = acc - mean;
    sred[grp][e] = diff * diff; __syncthreads();
    #pragma unroll
    for (int s = 32; s > 0; s >>= 1) {
        if (e < s) sred[grp][e] += sred[grp][e + s];
        __syncthreads();
    }
    float var = sred[grp][0] * (1.0f / 64.0f);
    float r = diff * rsqrtf(var + 1e-6f) * lng[e & 63] + lnb[e & 63];
    int widx = (bh * 64 + q) * 64 + e;
    if (widx < n_out) out[widx] = r;                   // [b][h][q][e]
}

// ---------------- fallback: zero-fill output ----------------------------------
__global__ void kz_zero(float* __restrict__ out, int n_out) {
    int i = blockIdx.x * 256 + threadIdx.x;
    if (i < n_out) out[i] = 0.0f;
}

// ---------------- launch ------------------------------------------------------
static bool size_ok(int got, int need_elems) {
    return got == need_elems || got == need_elems * 4;   // elements or bytes
}

extern "C" void kernel_launch(void* const* d_in, const int* in_sizes, int n_in,
                              void* d_out, int out_size) {
    int n_out = out_size;
    if (n_out == 65536 * 4 || n_out == 196608 * 4) n_out >>= 2;
    if (n_out < 0) n_out = 0;
    float* out = (float*)d_out;

    const int SZ_BIG = BSX * QL * INNER;       // 65536
    const int SZ_WI  = 2 * INNER * INNER;      // 524288
    const int SZ_DI  = VOC * DKV;              // 262144
    const int SZ_OW  = DKV * DKV;              // 4096
    const int SZ_V   = DKV;                    // 64

    const float *query = 0, *key = 0, *qpe = 0, *kpe = 0, *wi = 0, *dict = 0,
                *ow = 0, *vg = 0, *vb = 0, *lg = 0, *lb = 0;
    bool mapped = false;

    if (n_in >= 11) {
        const int sig[11] = {SZ_BIG, SZ_BIG, SZ_BIG, SZ_BIG, SZ_WI, SZ_DI,
                             SZ_V, SZ_V, SZ_OW, SZ_V, SZ_V};
        bool ok = true;
        for (int i = 0; i < 11; i++) ok = ok && size_ok(in_sizes[i], sig[i]);
        if (ok) {
            query = (const float*)d_in[0];  key = (const float*)d_in[1];
            qpe   = (const float*)d_in[2];  kpe = (const float*)d_in[3];
            wi    = (const float*)d_in[4];  dict = (const float*)d_in[5];
            vg    = (const float*)d_in[6];  vb  = (const float*)d_in[7];
            ow    = (const float*)d_in[8];  lg  = (const float*)d_in[9];
            lb    = (const float*)d_in[10];
            mapped = true;
        }
        if (!mapped) {
            const int alp[11] = {SZ_BIG, SZ_BIG, SZ_V, SZ_V, SZ_BIG, SZ_BIG,
                                 SZ_DI, SZ_V, SZ_V, SZ_OW, SZ_WI};
            bool ok2 = true;
            for (int i = 0; i < 11; i++) ok2 = ok2 && size_ok(in_sizes[i], alp[i]);
            if (ok2) {
                key  = (const float*)d_in[0];  kpe = (const float*)d_in[1];
                lb   = (const float*)d_in[2];  lg  = (const float*)d_in[3];
                qpe  = (const float*)d_in[4];  query = (const float*)d_in[5];
                dict = (const float*)d_in[6];  vb  = (const float*)d_in[7];
                vg   = (const float*)d_in[8];  ow  = (const float*)d_in[9];
                wi   = (const float*)d_in[10];
                mapped = true;
            }
        }
    }

    if (!mapped) {
        if (n_out > 0) kz_zero<<<(n_out + 255) / 256, 256>>>(out, n_out);
        return;
    }

    k0_dict <<<64, 256>>>(dict, vg, vb, ow);
    k1_proj <<<dim3(8, 16, 2), 128>>>(query, key, qpe, kpe, wi);
    kB_main <<<dim3(68, 16), 256>>>();
    kC_final<<<512, 128>>>(lg, lb, out, n_out);
}